// round 11
// baseline (speedup 1.0000x reference)
#include <cuda_runtime.h>
#include <cuda_bf16.h>
#include <cuda_fp16.h>
#include <cstdint>

#define BATCH 4
#define CCH   256
#define HW    4096
#define MID   64

using bf16 = __nv_bfloat16;

// ---------------- device-global scratch (allocation-free rule) --------------
__device__ __align__(1024) bf16 g_Ut[(size_t)BATCH * HW * CCH];   // [b][j][c]
__device__ __align__(1024) bf16 g_Tt[(size_t)BATCH * HW * MID];   // [b][i][m]
__device__ __align__(1024) bf16 g_Mt[MID * CCH];                  // [m][c]  Wq^T Wk2
__device__ __align__(1024) bf16 g_Wv[CCH * CCH];
__device__ __align__(1024) bf16 g_At[(size_t)BATCH * HW * MID];   // [b][j][m]
__device__ __align__(1024) uint8_t g_Vz8[(size_t)BATCH * CCH * HW]; // [b][c][i] e4m3
__device__ __align__(1024) uint8_t g_S8 [(size_t)BATCH * HW * HW];  // [b][j][i] e4m3 64MB
__device__ float g_Zp[(size_t)BATCH * 256 * HW];                  // partials
__device__ float g_Zi[BATCH * HW];                                // 4096/Z

// ---------------- PTX helpers ----------------------------------------------
__device__ __forceinline__ uint32_t smem_u32(const void* p) {
    uint32_t a;
    asm("{ .reg .u64 t; cvta.to.shared.u64 t, %1; cvt.u32.u64 %0, t; }"
        : "=r"(a) : "l"(p));
    return a;
}
__device__ __forceinline__ void cp16(uint32_t s, const void* g) {
    asm volatile("cp.async.cg.shared.global [%0], [%1], 16;" :: "r"(s), "l"(g));
}
#define CP_COMMIT() asm volatile("cp.async.commit_group;" ::: "memory")
#define CP_WAIT(n)  asm volatile("cp.async.wait_group %0;" :: "n"(n) : "memory")

__device__ __forceinline__ void ldsm4(uint32_t* r, uint32_t a) {
    asm volatile("ldmatrix.sync.aligned.m8n8.x4.shared.b16 {%0,%1,%2,%3}, [%4];"
                 : "=r"(r[0]), "=r"(r[1]), "=r"(r[2]), "=r"(r[3]) : "r"(a));
}
__device__ __forceinline__ void mma_bf16(float* d, const uint32_t* a,
                                         uint32_t b0, uint32_t b1) {
    asm volatile("mma.sync.aligned.m16n8k16.row.col.f32.bf16.bf16.f32 "
                 "{%0,%1,%2,%3}, {%4,%5,%6,%7}, {%8,%9}, {%0,%1,%2,%3};"
                 : "+f"(d[0]), "+f"(d[1]), "+f"(d[2]), "+f"(d[3])
                 : "r"(a[0]), "r"(a[1]), "r"(a[2]), "r"(a[3]), "r"(b0), "r"(b1));
}
__device__ __forceinline__ void mma_fp8(float* d, const uint32_t* a,
                                        uint32_t b0, uint32_t b1) {
    asm volatile("mma.sync.aligned.m16n8k32.row.col.f32.e4m3.e4m3.f32 "
                 "{%0,%1,%2,%3}, {%4,%5,%6,%7}, {%8,%9}, {%0,%1,%2,%3};"
                 : "+f"(d[0]), "+f"(d[1]), "+f"(d[2]), "+f"(d[3])
                 : "r"(a[0]), "r"(a[1]), "r"(a[2]), "r"(a[3]), "r"(b0), "r"(b1));
}
// pack 2 floats -> e4m3x2 (b16 dest; low byte = f0)
__device__ __forceinline__ uint16_t pack2_e4m3(float f0, float f1) {
    uint16_t v;
    asm("cvt.rn.satfinite.e4m3x2.f32 %0, %1, %2;" : "=h"(v) : "f"(f1), "f"(f0));
    return v;
}
__device__ __forceinline__ uint32_t pack4_e4m3(float f0, float f1, float f2, float f3) {
    uint32_t lo = pack2_e4m3(f0, f1), hi = pack2_e4m3(f2, f3);
    return (hi << 16) | lo;
}
// unpack e4m3x2 -> float2 (exact)
__device__ __forceinline__ float2 unpack2_e4m3(uint16_t p) {
    uint32_t h;
    asm("cvt.rn.f16x2.e4m3x2 %0, %1;" : "=r"(h) : "h"(p));
    return __half22float2(*reinterpret_cast<half2*>(&h));
}

#define EPI_STRIDE  136   // fp32 staging stride (elems)
#define S8_STRIDE   132   // fp8 staging stride (bytes)

// ---- main kernel smem: 3 stages x (A 16KB + B 16KB) ----
#define STAGE_SM  32768
#define SMEM_SM   (3 * STAGE_SM + 128)
// ---- A' kernel smem: 3 stages x (A 16KB + B 8KB) ----
#define STAGE_AT  24576
#define SMEM_AT   (3 * STAGE_AT + 128)

// load nrows x 128B rows, SW128 swizzle, NTH threads
template<int NROWS, int NTH>
__device__ __forceinline__ void ldtile(uint32_t sbuf, const char* g,
                                       size_t stride, int tid) {
#pragma unroll
    for (int u = 0; u < NROWS * 8 / NTH; ++u) {
        int idx = tid + u * NTH;
        int r = idx >> 3, s = idx & 7;
        cp16(sbuf + r * 128 + ((s ^ (r & 7)) << 4), g + (size_t)r * stride + (s << 4));
    }
}

// ---------------------------------------------------------------------------
// HMMA GEMM (256 thr): D[128 x 128] = A(128 rows) * B(128 rows)^T
// MODE 2 (bf16): S  A=At(j)  B=Tt(i)  K=64el  -> S8[j][i]=e4m3(exp(E)), Zp
// MODE 3 (bf16): Vz A=Wv(c)  B=Ut(i)  K=256el -> Vz8[c][i] = e4m3(V*4096/Z)
// ---------------------------------------------------------------------------
template<int MODE>
__global__ void __launch_bounds__(256, 2) gemm_hmma(const float* __restrict__ U,
                                                    const float* __restrict__ gammap,
                                                    float* __restrict__ Out)
{
    extern __shared__ char smem_raw[];
    uint32_t sb = (smem_u32(smem_raw) + 127u) & ~127u;
    const int tid = threadIdx.x, lane = tid & 31, wid = tid >> 5;
    const int wm = wid & 1, wn = wid >> 1;
    const int b = blockIdx.z;
    const int m0 = blockIdx.y * 128, n0 = blockIdx.x * 128;

    constexpr int NC = (MODE == 2) ? 1 : 4;

    const char *gA, *gB;
    size_t strA, strB;
    if (MODE == 2) {
        gA = (const char*)(g_At + ((size_t)b * HW + m0) * MID); strA = MID * 2;
        gB = (const char*)(g_Tt + ((size_t)b * HW + n0) * MID); strB = MID * 2;
    } else {
        gA = (const char*)(g_Wv + (size_t)m0 * CCH);            strA = CCH * 2;
        gB = (const char*)(g_Ut + ((size_t)b * HW + n0) * CCH); strB = CCH * 2;
    }

    float acc[4][4][4] = {};

    ldtile<128, 256>(sb, gA, strA, tid);
    ldtile<128, 256>(sb + 16384, gB, strB, tid);
    CP_COMMIT();
    if (NC > 1) {
        ldtile<128, 256>(sb + STAGE_SM, gA + 128, strA, tid);
        ldtile<128, 256>(sb + STAGE_SM + 16384, gB + 128, strB, tid);
    }
    CP_COMMIT();

#pragma unroll 1
    for (int n = 0; n < NC; ++n) {
        CP_WAIT(1);
        __syncthreads();
        if (n + 2 < NC) {
            uint32_t sp = sb + ((n + 2) % 3) * STAGE_SM;
            ldtile<128, 256>(sp, gA + (size_t)(n + 2) * 128, strA, tid);
            ldtile<128, 256>(sp + 16384, gB + (size_t)(n + 2) * 128, strB, tid);
        }
        CP_COMMIT();

        uint32_t sA = sb + (n % 3) * STAGE_SM;
        uint32_t sB = sA + 16384;
#pragma unroll
        for (int kt = 0; kt < 4; ++kt) {
            uint32_t af[4][4], bfr[2][4];
            int s16 = kt * 2 + (lane >> 4);
#pragma unroll
            for (int mt = 0; mt < 4; ++mt) {
                int row = wm * 64 + mt * 16 + (lane & 15);
                ldsm4(af[mt], sA + row * 128 + ((s16 ^ (row & 7)) << 4));
            }
#pragma unroll
            for (int g = 0; g < 2; ++g) {
                int row = wn * 32 + g * 16 + (lane & 15);
                ldsm4(bfr[g], sB + row * 128 + ((s16 ^ (row & 7)) << 4));
            }
#pragma unroll
            for (int mt = 0; mt < 4; ++mt)
#pragma unroll
                for (int nt = 0; nt < 4; ++nt)
                    mma_bf16(acc[mt][nt], af[mt],
                             bfr[nt >> 1][nt & 1], bfr[nt >> 1][(nt & 1) + 2]);
        }
    }
    CP_WAIT(0);
    __syncthreads();

    const int r0 = wm * 64 + (lane >> 2);
    const int c0 = wn * 32 + 2 * (lane & 3);

    if (MODE == 2) {
        // exp -> e4m3 staging -> coalesced store + Z partials from rounded vals
        uint8_t* st8 = (uint8_t*)(smem_raw + (sb - smem_u32(smem_raw)));
#pragma unroll
        for (int mt = 0; mt < 4; ++mt)
#pragma unroll
            for (int nt = 0; nt < 4; ++nt) {
                float v0 = __expf(acc[mt][nt][0]), v1 = __expf(acc[mt][nt][1]);
                float v2 = __expf(acc[mt][nt][2]), v3 = __expf(acc[mt][nt][3]);
                int r = r0 + mt * 16, c = c0 + nt * 8;
                *(uint16_t*)&st8[r * S8_STRIDE + c] = pack2_e4m3(v0, v1);
                *(uint16_t*)&st8[(r + 8) * S8_STRIDE + c] = pack2_e4m3(v2, v3);
            }
        __syncthreads();
        uint8_t* Sp = g_S8 + (size_t)b * HW * HW;
        int ch = tid & 31, h = tid >> 5;           // 8 groups of 16 rows
        float zcol[4] = {0, 0, 0, 0};
#pragma unroll
        for (int r = 0; r < 16; ++r) {
            int row = h * 16 + r;
            uint32_t v = *(uint32_t*)&st8[row * S8_STRIDE + ch * 4];
            float2 fa = unpack2_e4m3((uint16_t)v);
            float2 fb = unpack2_e4m3((uint16_t)(v >> 16));
            zcol[0] += fa.x; zcol[1] += fa.y; zcol[2] += fb.x; zcol[3] += fb.y;
            *(uint32_t*)&Sp[(size_t)(m0 + row) * HW + n0 + ch * 4] = v;
        }
        float4 z4 = make_float4(zcol[0], zcol[1], zcol[2], zcol[3]);
        *(float4*)&g_Zp[((size_t)b * 256 + blockIdx.y * 8 + h) * HW + n0 + ch * 4] = z4;
    } else {  // MODE 3
        float* st = (float*)(smem_raw + (sb - smem_u32(smem_raw)));
#pragma unroll
        for (int mt = 0; mt < 4; ++mt)
#pragma unroll
            for (int nt = 0; nt < 4; ++nt) {
                int r = r0 + mt * 16, c = c0 + nt * 8;
                *(float2*)&st[r * EPI_STRIDE + c] = make_float2(acc[mt][nt][0], acc[mt][nt][1]);
                *(float2*)&st[(r + 8) * EPI_STRIDE + c] = make_float2(acc[mt][nt][2], acc[mt][nt][3]);
            }
        __syncthreads();
#pragma unroll
        for (int u = 0; u < 16; ++u) {
            int idx = tid + u * 256;
            int row = idx >> 5, ch = idx & 31;
            float4 v = *(float4*)&st[row * EPI_STRIDE + ch * 4];
            float4 z = *(const float4*)&g_Zi[b * HW + n0 + ch * 4];   // = 4096/Z
            uint32_t p = pack4_e4m3(v.x * z.x, v.y * z.y, v.z * z.z, v.w * z.w);
            *(uint32_t*)&g_Vz8[((size_t)b * CCH + m0 + row) * HW + n0 + ch * 4] = p;
        }
    }
}

// ---------------------------------------------------------------------------
// Output GEMM (fp8, 512 thr, 4x4 warp grid, 32x32 warp tiles, 2 CTA/SM):
// out[c][j] = gamma/4096 * sum_i Vz8[c][i] S8[j][i] + U[c][j],  K = 4096 el
// ---------------------------------------------------------------------------
__global__ void __launch_bounds__(512, 2) gemm_out(const float* __restrict__ U,
                                                   const float* __restrict__ gammap,
                                                   float* __restrict__ Out)
{
    extern __shared__ char smem_raw[];
    uint32_t sb = (smem_u32(smem_raw) + 127u) & ~127u;
    const int tid = threadIdx.x, lane = tid & 31, wid = tid >> 5;
    const int wm = wid & 3, wn = wid >> 2;          // 4 x 4 warps
    const int b = blockIdx.z;
    const int m0 = blockIdx.y * 128, n0 = blockIdx.x * 128;

    constexpr int NC = 32;   // 32 x 128B fp8 chunks = 4096 K elements

    const char* gA = (const char*)(g_Vz8 + (size_t)b * CCH * HW + (size_t)m0 * HW);
    const char* gB = (const char*)(g_S8 + (size_t)b * HW * HW + (size_t)n0 * HW);
    const size_t strA = HW, strB = HW;

    float acc[2][4][4] = {};

    ldtile<128, 512>(sb, gA, strA, tid);
    ldtile<128, 512>(sb + 16384, gB, strB, tid);
    CP_COMMIT();
    ldtile<128, 512>(sb + STAGE_SM, gA + 128, strA, tid);
    ldtile<128, 512>(sb + STAGE_SM + 16384, gB + 128, strB, tid);
    CP_COMMIT();

#pragma unroll 1
    for (int n = 0; n < NC; ++n) {
        CP_WAIT(1);
        __syncthreads();
        if (n + 2 < NC) {
            uint32_t sp = sb + ((n + 2) % 3) * STAGE_SM;
            ldtile<128, 512>(sp, gA + (size_t)(n + 2) * 128, strA, tid);
            ldtile<128, 512>(sp + 16384, gB + (size_t)(n + 2) * 128, strB, tid);
        }
        CP_COMMIT();

        uint32_t sA = sb + (n % 3) * STAGE_SM;
        uint32_t sB = sA + 16384;
#pragma unroll
        for (int kt = 0; kt < 4; ++kt) {
            uint32_t af[2][4], bfr[2][4];
            int s16 = kt * 2 + (lane >> 4);
#pragma unroll
            for (int mt = 0; mt < 2; ++mt) {
                int row = wm * 32 + mt * 16 + (lane & 15);
                ldsm4(af[mt], sA + row * 128 + ((s16 ^ (row & 7)) << 4));
            }
#pragma unroll
            for (int g = 0; g < 2; ++g) {
                int row = wn * 32 + g * 16 + (lane & 15);
                ldsm4(bfr[g], sB + row * 128 + ((s16 ^ (row & 7)) << 4));
            }
#pragma unroll
            for (int mt = 0; mt < 2; ++mt)
#pragma unroll
                for (int nt = 0; nt < 4; ++nt)
                    mma_fp8(acc[mt][nt], af[mt],
                            bfr[nt >> 1][nt & 1], bfr[nt >> 1][(nt & 1) + 2]);
        }
    }
    CP_WAIT(0);
    __syncthreads();

    // fp32 staging 128 x 136, fused gamma*x + U store
    const int r0 = wm * 32 + (lane >> 2);
    const int c0 = wn * 32 + 2 * (lane & 3);
    float* st = (float*)(smem_raw + (sb - smem_u32(smem_raw)));
    float gamma = __ldg(gammap) * (1.0f / 4096.0f);
#pragma unroll
    for (int mt = 0; mt < 2; ++mt)
#pragma unroll
        for (int nt = 0; nt < 4; ++nt) {
            int r = r0 + mt * 16, c = c0 + nt * 8;
            *(float2*)&st[r * EPI_STRIDE + c] = make_float2(acc[mt][nt][0], acc[mt][nt][1]);
            *(float2*)&st[(r + 8) * EPI_STRIDE + c] = make_float2(acc[mt][nt][2], acc[mt][nt][3]);
        }
    __syncthreads();
#pragma unroll
    for (int u = 0; u < 8; ++u) {
        int idx = tid + u * 512;
        int row = idx >> 5, ch = idx & 31;
        float4 v = *(float4*)&st[row * EPI_STRIDE + ch * 4];
        size_t off = ((size_t)b * CCH + m0 + row) * HW + n0 + ch * 4;
        float4 uv = *(const float4*)(U + off);
        float4 o;
        o.x = fmaf(gamma, v.x, uv.x); o.y = fmaf(gamma, v.y, uv.y);
        o.z = fmaf(gamma, v.z, uv.z); o.w = fmaf(gamma, v.w, uv.w);
        *(float4*)(Out + off) = o;
    }
}

// ---------------------------------------------------------------------------
// A' GEMM: D[128 x 64] = Ut(128 j-rows, K=256) * Mt(64 m-rows, K=256)^T
// ---------------------------------------------------------------------------
__global__ void __launch_bounds__(256, 2) gemm_at()
{
    extern __shared__ char smem_raw[];
    uint32_t sb = (smem_u32(smem_raw) + 127u) & ~127u;
    const int tid = threadIdx.x, lane = tid & 31, wid = tid >> 5;
    const int wm = wid >> 1, wn = wid & 1;
    const int b = blockIdx.z;
    const int m0 = blockIdx.y * 128;

    constexpr int NC = CCH / 64;   // 4
    const char* gA = (const char*)(g_Ut + ((size_t)b * HW + m0) * CCH);
    const char* gB = (const char*)g_Mt;
    const size_t strA = CCH * 2, strB = CCH * 2;

    float acc[2][4][4] = {};

    ldtile<128, 256>(sb, gA, strA, tid);
    ldtile<64, 256>(sb + 16384, gB, strB, tid);
    CP_COMMIT();
    ldtile<128, 256>(sb + STAGE_AT, gA + 128, strA, tid);
    ldtile<64, 256>(sb + STAGE_AT + 16384, gB + 128, strB, tid);
    CP_COMMIT();

#pragma unroll 1
    for (int n = 0; n < NC; ++n) {
        CP_WAIT(1);
        __syncthreads();
        if (n + 2 < NC) {
            uint32_t sp = sb + ((n + 2) % 3) * STAGE_AT;
            ldtile<128, 256>(sp, gA + (size_t)(n + 2) * 128, strA, tid);
            ldtile<64, 256>(sp + 16384, gB + (size_t)(n + 2) * 128, strB, tid);
        }
        CP_COMMIT();

        uint32_t sA = sb + (n % 3) * STAGE_AT;
        uint32_t sB = sA + 16384;
#pragma unroll
        for (int kt = 0; kt < 4; ++kt) {
            uint32_t af[2][4], bfr[2][4];
            int s16 = kt * 2 + (lane >> 4);
#pragma unroll
            for (int mt = 0; mt < 2; ++mt) {
                int row = wm * 32 + mt * 16 + (lane & 15);
                ldsm4(af[mt], sA + row * 128 + ((s16 ^ (row & 7)) << 4));
            }
#pragma unroll
            for (int g = 0; g < 2; ++g) {
                int row = wn * 32 + g * 16 + (lane & 15);
                ldsm4(bfr[g], sB + row * 128 + ((s16 ^ (row & 7)) << 4));
            }
#pragma unroll
            for (int mt = 0; mt < 2; ++mt)
#pragma unroll
                for (int nt = 0; nt < 4; ++nt)
                    mma_bf16(acc[mt][nt], af[mt],
                             bfr[nt >> 1][nt & 1], bfr[nt >> 1][(nt & 1) + 2]);
        }
    }
    CP_WAIT(0);
    __syncthreads();

    const int r0 = wm * 32 + (lane >> 2);
    const int c0 = wn * 32 + 2 * (lane & 3);
    bf16* st = (bf16*)(smem_raw + (sb - smem_u32(smem_raw)));
#pragma unroll
    for (int mt = 0; mt < 2; ++mt)
#pragma unroll
        for (int nt = 0; nt < 4; ++nt) {
            int r = r0 + mt * 16, c = c0 + nt * 8;
            *(__nv_bfloat162*)&st[r * 72 + c] =
                __floats2bfloat162_rn(acc[mt][nt][0], acc[mt][nt][1]);
            *(__nv_bfloat162*)&st[(r + 8) * 72 + c] =
                __floats2bfloat162_rn(acc[mt][nt][2], acc[mt][nt][3]);
        }
    __syncthreads();
    bf16* dst = g_At + ((size_t)b * HW + m0) * MID;
#pragma unroll
    for (int u = 0; u < 8; ++u) {
        int idx = tid + u * 256;
        int row = idx >> 4, ch = idx & 15;
        uint2 v = *(uint2*)&st[row * 72 + ch * 4];
        *(uint2*)&dst[(size_t)row * MID + ch * 4] = v;
    }
}

// ---------------------------------------------------------------------------
// prep kernels
// ---------------------------------------------------------------------------
__global__ void wmix_kernel(const float* __restrict__ qw,
                            const float* __restrict__ kw2) {
    int m = blockIdx.x, c = threadIdx.x;
    float acc = 0.0f;
#pragma unroll 8
    for (int o = 0; o < CCH; ++o)
        acc += qw[o * CCH + c] * kw2[o * MID + m];
    g_Mt[m * CCH + c] = __float2bfloat16(acc);
}

__global__ void wconv_kernel(const float* __restrict__ vw) {
    int i = blockIdx.x * 256 + threadIdx.x;
    g_Wv[i] = __float2bfloat16(vw[i]);
}

__global__ void transU_kernel(const float* __restrict__ U) {
    __shared__ float t[32][33];
    int b = blockIdx.z, c0 = blockIdx.y * 32, j0 = blockIdx.x * 32;
    int tx = threadIdx.x, ty = threadIdx.y;
    const float* Ub = U + ((size_t)b * CCH + c0) * HW + j0;
#pragma unroll
    for (int k = 0; k < 4; ++k)
        t[ty + 8 * k][tx] = Ub[(size_t)(ty + 8 * k) * HW + tx];
    __syncthreads();
    bf16* Utb = g_Ut + ((size_t)b * HW + j0) * CCH + c0;
#pragma unroll
    for (int k = 0; k < 4; ++k)
        Utb[(size_t)(ty + 8 * k) * CCH + tx] = __float2bfloat16(t[tx][ty + 8 * k]);
}

__global__ void keymid_kernel(const float* __restrict__ bmap,
                              const float* __restrict__ w1,
                              const float* __restrict__ bs,
                              const float* __restrict__ bbias,
                              const float* __restrict__ bmean,
                              const float* __restrict__ bvar) {
    int idx = blockIdx.x * 256 + threadIdx.x;
    int m = idx & 63, p = (idx >> 6) & (HW - 1), b = idx >> 18;
    float inv = bs[m] * rsqrtf(bvar[m] + 1e-5f);
    float a   = w1[m] * inv;
    float bb  = bbias[m] - bmean[m] * inv;
    int y = p >> 6, x = p & 63;
    float s = bmap[b * 16384 + y * 256 + x * 2];
    g_Tt[idx] = __float2bfloat16(fmaxf(fmaf(a, s, bb), 0.0f));
}

__global__ void zinv_kernel() {
    int t = blockIdx.x * 256 + threadIdx.x;     // BATCH*HW
    int b = t >> 12, i = t & (HW - 1);
    float s = 0.0f;
#pragma unroll 8
    for (int p = 0; p < 256; ++p)
        s += g_Zp[((size_t)b * 256 + p) * HW + i];
    g_Zi[t] = 4096.0f / s;       // 4096 scale folded here (undone by gamma/4096)
}

// ---------------------------------------------------------------------------
extern "C" void kernel_launch(void* const* d_in, const int* in_sizes, int n_in,
                              void* d_out, int out_size)
{
    const float* bmap     = (const float*)d_in[0];
    const float* U        = (const float*)d_in[1];
    const float* key_w1   = (const float*)d_in[2];
    const float* bn_scale = (const float*)d_in[3];
    const float* bn_bias  = (const float*)d_in[4];
    const float* bn_mean  = (const float*)d_in[5];
    const float* bn_var   = (const float*)d_in[6];
    const float* key_w2   = (const float*)d_in[7];
    const float* query_w  = (const float*)d_in[8];
    const float* value_w  = (const float*)d_in[9];
    const float* gamma    = (const float*)d_in[10];
    float* out = (float*)d_out;

    cudaFuncSetAttribute(gemm_hmma<2>, cudaFuncAttributeMaxDynamicSharedMemorySize, SMEM_SM);
    cudaFuncSetAttribute(gemm_hmma<3>, cudaFuncAttributeMaxDynamicSharedMemorySize, SMEM_SM);
    cudaFuncSetAttribute(gemm_out,     cudaFuncAttributeMaxDynamicSharedMemorySize, SMEM_SM);
    cudaFuncSetAttribute(gemm_at,      cudaFuncAttributeMaxDynamicSharedMemorySize, SMEM_AT);

    // prep
    wmix_kernel<<<MID, CCH>>>(query_w, key_w2);
    wconv_kernel<<<256, 256>>>(value_w);
    transU_kernel<<<dim3(HW / 32, CCH / 32, BATCH), dim3(32, 8)>>>(U);
    keymid_kernel<<<(BATCH * HW * MID) / 256, 256>>>(bmap, key_w1, bn_scale,
                                                     bn_bias, bn_mean, bn_var);
    // A'[j][m] = Ut . Mt^T
    gemm_at<<<dim3(1, 32, BATCH), 256, SMEM_AT>>>();
    // S8[j][i] = e4m3(exp(A'_j . T_i)) + Z partials   (K=64)
    gemm_hmma<2><<<dim3(32, 32, BATCH), 256, SMEM_SM>>>(U, gamma, out);
    // Zi = 4096/Z
    zinv_kernel<<<(BATCH * HW) / 256, 256>>>();
    // Vz8[c][i] = e4m3((Wv @ U)[c][i] * 4096/Z[i])
    gemm_hmma<3><<<dim3(32, 2, BATCH), 256, SMEM_SM>>>(U, gamma, out);
    // out[c][j] = gamma/4096 * sum_i Vz8[c][i] S8[j][i] + U[c][j]   (fp8, 512 thr)
    gemm_out<<<dim3(32, 2, BATCH), 512, SMEM_SM>>>(U, gamma, out);
}

// round 13
// speedup vs baseline: 1.1795x; 1.1795x over previous
#include <cuda_runtime.h>
#include <cuda_bf16.h>
#include <cuda_fp16.h>
#include <cstdint>

#define BATCH 4
#define CCH   256
#define HW    4096
#define MID   64

using bf16 = __nv_bfloat16;

// ---------------- device-global scratch (allocation-free rule) --------------
__device__ __align__(1024) bf16 g_Ut[(size_t)BATCH * HW * CCH];   // [b][j][c]
__device__ __align__(1024) bf16 g_Tt[(size_t)BATCH * HW * MID];   // [b][i][m]
__device__ __align__(1024) bf16 g_Mt[MID * CCH];                  // [m][c]  Wq^T Wk2
__device__ __align__(1024) bf16 g_Wv[CCH * CCH];
__device__ __align__(1024) bf16 g_At[(size_t)BATCH * HW * MID];   // [b][j][m]
__device__ __align__(1024) uint8_t g_Vz8[(size_t)BATCH * CCH * HW]; // [b][c][i] e4m3
__device__ __align__(1024) uint8_t g_S8 [(size_t)BATCH * HW * HW];  // [b][j][i] e4m3 64MB
__device__ float g_Zp[(size_t)BATCH * 32 * HW];                   // 2MB partials
__device__ float g_Zi[BATCH * HW];                                // 4096/Z

// ---------------- PTX helpers ----------------------------------------------
__device__ __forceinline__ uint32_t smem_u32(const void* p) {
    uint32_t a;
    asm("{ .reg .u64 t; cvta.to.shared.u64 t, %1; cvt.u32.u64 %0, t; }"
        : "=r"(a) : "l"(p));
    return a;
}
__device__ __forceinline__ void cp16(uint32_t s, const void* g) {
    asm volatile("cp.async.cg.shared.global [%0], [%1], 16;" :: "r"(s), "l"(g));
}
#define CP_COMMIT() asm volatile("cp.async.commit_group;" ::: "memory")
#define CP_WAIT(n)  asm volatile("cp.async.wait_group %0;" :: "n"(n) : "memory")

__device__ __forceinline__ void ldsm4(uint32_t* r, uint32_t a) {
    asm volatile("ldmatrix.sync.aligned.m8n8.x4.shared.b16 {%0,%1,%2,%3}, [%4];"
                 : "=r"(r[0]), "=r"(r[1]), "=r"(r[2]), "=r"(r[3]) : "r"(a));
}
__device__ __forceinline__ void mma_bf16(float* d, const uint32_t* a,
                                         uint32_t b0, uint32_t b1) {
    asm volatile("mma.sync.aligned.m16n8k16.row.col.f32.bf16.bf16.f32 "
                 "{%0,%1,%2,%3}, {%4,%5,%6,%7}, {%8,%9}, {%0,%1,%2,%3};"
                 : "+f"(d[0]), "+f"(d[1]), "+f"(d[2]), "+f"(d[3])
                 : "r"(a[0]), "r"(a[1]), "r"(a[2]), "r"(a[3]), "r"(b0), "r"(b1));
}
__device__ __forceinline__ void mma_fp8(float* d, const uint32_t* a,
                                        uint32_t b0, uint32_t b1) {
    asm volatile("mma.sync.aligned.m16n8k32.row.col.f32.e4m3.e4m3.f32 "
                 "{%0,%1,%2,%3}, {%4,%5,%6,%7}, {%8,%9}, {%0,%1,%2,%3};"
                 : "+f"(d[0]), "+f"(d[1]), "+f"(d[2]), "+f"(d[3])
                 : "r"(a[0]), "r"(a[1]), "r"(a[2]), "r"(a[3]), "r"(b0), "r"(b1));
}
// pack 2 floats -> e4m3x2 (b16 dest; low byte = f0)
__device__ __forceinline__ uint16_t pack2_e4m3(float f0, float f1) {
    uint16_t v;
    asm("cvt.rn.satfinite.e4m3x2.f32 %0, %1, %2;" : "=h"(v) : "f"(f1), "f"(f0));
    return v;
}
__device__ __forceinline__ uint32_t pack4_e4m3(float f0, float f1, float f2, float f3) {
    uint32_t lo = pack2_e4m3(f0, f1), hi = pack2_e4m3(f2, f3);
    return (hi << 16) | lo;
}
// unpack e4m3x2 -> float2 (exact)
__device__ __forceinline__ float2 unpack2_e4m3(uint16_t p) {
    uint32_t h;
    asm("cvt.rn.f16x2.e4m3x2 %0, %1;" : "=r"(h) : "h"(p));
    return __half22float2(*reinterpret_cast<half2*>(&h));
}

#define EPI_STRIDE  136   // fp32 staging stride (elems)
#define S8_STRIDE   132   // fp8 staging stride (bytes)
#define ZSM_OFF     20480 // Z reduction scratch (beyond 128*132 S8 staging)

// ---- main kernel smem: 3 stages x (A 16KB + B 16KB) ----
#define STAGE_SM  32768
#define SMEM_SM   (3 * STAGE_SM + 128)
// ---- A' kernel smem: 3 stages x (A 16KB + B 8KB) ----
#define STAGE_AT  24576
#define SMEM_AT   (3 * STAGE_AT + 128)

// load nrows x 128B rows, SW128 swizzle, 256 threads
template<int NROWS>
__device__ __forceinline__ void ldtile(uint32_t sbuf, const char* g,
                                       size_t stride, int tid) {
#pragma unroll
    for (int u = 0; u < NROWS / 32; ++u) {
        int idx = tid + u * 256;
        int r = idx >> 3, s = idx & 7;
        cp16(sbuf + r * 128 + ((s ^ (r & 7)) << 4), g + (size_t)r * stride + (s << 4));
    }
}

// ---------------------------------------------------------------------------
// HMMA GEMM (256 thr, 2 CTA/SM, 64x32 warp tiles): D[128x128] = A * B^T
// MODE 2 (bf16): S  A=At(j)  B=Tt(i)  K=64el  -> S8[j][i]=e4m3(exp(E)), Zp
// MODE 3 (bf16): Vz A=Wv(c)  B=Ut(i)  K=256el -> Vz8[c][i] = e4m3(V*4096/Z)
// MODE 4 (fp8):  Out A=Vz8(c) B=S8(j) K=4096el-> out=gamma/4096*x+U
// ---------------------------------------------------------------------------
template<int MODE>
__global__ void __launch_bounds__(256, 2) gemm_hmma(const float* __restrict__ U,
                                                    const float* __restrict__ gammap,
                                                    float* __restrict__ Out)
{
    extern __shared__ char smem_raw[];
    uint32_t sb = (smem_u32(smem_raw) + 127u) & ~127u;
    const int tid = threadIdx.x, lane = tid & 31, wid = tid >> 5;
    const int wm = wid & 1, wn = wid >> 1;
    const int b = blockIdx.z;
    const int m0 = blockIdx.y * 128, n0 = blockIdx.x * 128;

    constexpr int NC = (MODE == 2) ? 1 : (MODE == 3 ? 4 : 32);

    const char *gA, *gB;
    size_t strA, strB;
    if (MODE == 2) {
        gA = (const char*)(g_At + ((size_t)b * HW + m0) * MID); strA = MID * 2;
        gB = (const char*)(g_Tt + ((size_t)b * HW + n0) * MID); strB = MID * 2;
    } else if (MODE == 3) {
        gA = (const char*)(g_Wv + (size_t)m0 * CCH);            strA = CCH * 2;
        gB = (const char*)(g_Ut + ((size_t)b * HW + n0) * CCH); strB = CCH * 2;
    } else {
        gA = (const char*)(g_Vz8 + (size_t)b * CCH * HW + (size_t)m0 * HW); strA = HW;
        gB = (const char*)(g_S8 + (size_t)b * HW * HW + (size_t)n0 * HW);   strB = HW;
    }

    float acc[4][4][4] = {};

    ldtile<128>(sb, gA, strA, tid);
    ldtile<128>(sb + 16384, gB, strB, tid);
    CP_COMMIT();
    if (NC > 1) {
        ldtile<128>(sb + STAGE_SM, gA + 128, strA, tid);
        ldtile<128>(sb + STAGE_SM + 16384, gB + 128, strB, tid);
    }
    CP_COMMIT();

#pragma unroll 1
    for (int n = 0; n < NC; ++n) {
        CP_WAIT(1);
        __syncthreads();
        if (n + 2 < NC) {
            uint32_t sp = sb + ((n + 2) % 3) * STAGE_SM;
            ldtile<128>(sp, gA + (size_t)(n + 2) * 128, strA, tid);
            ldtile<128>(sp + 16384, gB + (size_t)(n + 2) * 128, strB, tid);
        }
        CP_COMMIT();

        uint32_t sA = sb + (n % 3) * STAGE_SM;
        uint32_t sB = sA + 16384;
#pragma unroll
        for (int kt = 0; kt < 4; ++kt) {
            uint32_t af[4][4], bfr[2][4];
            int s16 = kt * 2 + (lane >> 4);
#pragma unroll
            for (int mt = 0; mt < 4; ++mt) {
                int row = wm * 64 + mt * 16 + (lane & 15);
                ldsm4(af[mt], sA + row * 128 + ((s16 ^ (row & 7)) << 4));
            }
#pragma unroll
            for (int g = 0; g < 2; ++g) {
                int row = wn * 32 + g * 16 + (lane & 15);
                ldsm4(bfr[g], sB + row * 128 + ((s16 ^ (row & 7)) << 4));
            }
#pragma unroll
            for (int mt = 0; mt < 4; ++mt)
#pragma unroll
                for (int nt = 0; nt < 4; ++nt) {
                    if (MODE == 4)
                        mma_fp8(acc[mt][nt], af[mt],
                                bfr[nt >> 1][nt & 1], bfr[nt >> 1][(nt & 1) + 2]);
                    else
                        mma_bf16(acc[mt][nt], af[mt],
                                 bfr[nt >> 1][nt & 1], bfr[nt >> 1][(nt & 1) + 2]);
                }
        }
    }
    CP_WAIT(0);
    __syncthreads();

    const int r0 = wm * 64 + (lane >> 2);
    const int c0 = wn * 32 + 2 * (lane & 3);

    if (MODE == 2) {
        // exp -> e4m3 staging -> coalesced store + in-CTA reduced Z partials
        char* smem_base = smem_raw + (sb - smem_u32(smem_raw));
        uint8_t* st8 = (uint8_t*)smem_base;
#pragma unroll
        for (int mt = 0; mt < 4; ++mt)
#pragma unroll
            for (int nt = 0; nt < 4; ++nt) {
                float v0 = __expf(acc[mt][nt][0]), v1 = __expf(acc[mt][nt][1]);
                float v2 = __expf(acc[mt][nt][2]), v3 = __expf(acc[mt][nt][3]);
                int r = r0 + mt * 16, c = c0 + nt * 8;
                *(uint16_t*)&st8[r * S8_STRIDE + c] = pack2_e4m3(v0, v1);
                *(uint16_t*)&st8[(r + 8) * S8_STRIDE + c] = pack2_e4m3(v2, v3);
            }
        __syncthreads();
        uint8_t* Sp = g_S8 + (size_t)b * HW * HW;
        int ch = tid & 31, h = tid >> 5;           // 8 groups of 16 rows
        float zcol[4] = {0, 0, 0, 0};
#pragma unroll
        for (int r = 0; r < 16; ++r) {
            int row = h * 16 + r;
            uint32_t v = *(uint32_t*)&st8[row * S8_STRIDE + ch * 4];
            float2 fa = unpack2_e4m3((uint16_t)v);
            float2 fb = unpack2_e4m3((uint16_t)(v >> 16));
            zcol[0] += fa.x; zcol[1] += fa.y; zcol[2] += fb.x; zcol[3] += fb.y;
            *(uint32_t*)&Sp[(size_t)(m0 + row) * HW + n0 + ch * 4] = v;
        }
        // in-CTA reduction across the 8 h-groups (fixed order, deterministic)
        float4* zsm = (float4*)(smem_base + ZSM_OFF);
        zsm[h * 32 + ch] = make_float4(zcol[0], zcol[1], zcol[2], zcol[3]);
        __syncthreads();
        if (tid < 32) {
            float4 s = zsm[tid];
#pragma unroll
            for (int hh = 1; hh < 8; ++hh) {
                float4 t4 = zsm[hh * 32 + tid];
                s.x += t4.x; s.y += t4.y; s.z += t4.z; s.w += t4.w;
            }
            *(float4*)&g_Zp[((size_t)b * 32 + blockIdx.y) * HW + n0 + tid * 4] = s;
        }
    } else if (MODE == 3) {
        float* st = (float*)(smem_raw + (sb - smem_u32(smem_raw)));
#pragma unroll
        for (int mt = 0; mt < 4; ++mt)
#pragma unroll
            for (int nt = 0; nt < 4; ++nt) {
                int r = r0 + mt * 16, c = c0 + nt * 8;
                *(float2*)&st[r * EPI_STRIDE + c] = make_float2(acc[mt][nt][0], acc[mt][nt][1]);
                *(float2*)&st[(r + 8) * EPI_STRIDE + c] = make_float2(acc[mt][nt][2], acc[mt][nt][3]);
            }
        __syncthreads();
#pragma unroll
        for (int u = 0; u < 16; ++u) {
            int idx = tid + u * 256;
            int row = idx >> 5, ch = idx & 31;
            float4 v = *(float4*)&st[row * EPI_STRIDE + ch * 4];
            float4 z = *(const float4*)&g_Zi[b * HW + n0 + ch * 4];   // = 4096/Z
            uint32_t p = pack4_e4m3(v.x * z.x, v.y * z.y, v.z * z.z, v.w * z.w);
            *(uint32_t*)&g_Vz8[((size_t)b * CCH + m0 + row) * HW + n0 + ch * 4] = p;
        }
    } else {  // MODE 4
        float* st = (float*)(smem_raw + (sb - smem_u32(smem_raw)));
        float gamma = __ldg(gammap) * (1.0f / 4096.0f);
#pragma unroll
        for (int mt = 0; mt < 4; ++mt)
#pragma unroll
            for (int nt = 0; nt < 4; ++nt) {
                int r = r0 + mt * 16, c = c0 + nt * 8;
                *(float2*)&st[r * EPI_STRIDE + c] = make_float2(acc[mt][nt][0], acc[mt][nt][1]);
                *(float2*)&st[(r + 8) * EPI_STRIDE + c] = make_float2(acc[mt][nt][2], acc[mt][nt][3]);
            }
        __syncthreads();
#pragma unroll
        for (int u = 0; u < 16; ++u) {
            int idx = tid + u * 256;
            int row = idx >> 5, ch = idx & 31;
            float4 v = *(float4*)&st[row * EPI_STRIDE + ch * 4];
            size_t off = ((size_t)b * CCH + m0 + row) * HW + n0 + ch * 4;
            float4 uv = *(const float4*)(U + off);
            float4 o;
            o.x = fmaf(gamma, v.x, uv.x); o.y = fmaf(gamma, v.y, uv.y);
            o.z = fmaf(gamma, v.z, uv.z); o.w = fmaf(gamma, v.w, uv.w);
            *(float4*)(Out + off) = o;
        }
    }
}

// ---------------------------------------------------------------------------
// A' GEMM: D[128 x 64] = Ut(128 j-rows, K=256) * Mt(64 m-rows, K=256)^T
// ---------------------------------------------------------------------------
__global__ void __launch_bounds__(256, 2) gemm_at()
{
    extern __shared__ char smem_raw[];
    uint32_t sb = (smem_u32(smem_raw) + 127u) & ~127u;
    const int tid = threadIdx.x, lane = tid & 31, wid = tid >> 5;
    const int wm = wid >> 1, wn = wid & 1;
    const int b = blockIdx.z;
    const int m0 = blockIdx.y * 128;

    constexpr int NC = CCH / 64;   // 4
    const char* gA = (const char*)(g_Ut + ((size_t)b * HW + m0) * CCH);
    const char* gB = (const char*)g_Mt;
    const size_t strA = CCH * 2, strB = CCH * 2;

    float acc[2][4][4] = {};

    ldtile<128>(sb, gA, strA, tid);
    ldtile<64>(sb + 16384, gB, strB, tid);
    CP_COMMIT();
    ldtile<128>(sb + STAGE_AT, gA + 128, strA, tid);
    ldtile<64>(sb + STAGE_AT + 16384, gB + 128, strB, tid);
    CP_COMMIT();

#pragma unroll 1
    for (int n = 0; n < NC; ++n) {
        CP_WAIT(1);
        __syncthreads();
        if (n + 2 < NC) {
            uint32_t sp = sb + ((n + 2) % 3) * STAGE_AT;
            ldtile<128>(sp, gA + (size_t)(n + 2) * 128, strA, tid);
            ldtile<64>(sp + 16384, gB + (size_t)(n + 2) * 128, strB, tid);
        }
        CP_COMMIT();

        uint32_t sA = sb + (n % 3) * STAGE_AT;
        uint32_t sB = sA + 16384;
#pragma unroll
        for (int kt = 0; kt < 4; ++kt) {
            uint32_t af[2][4], bfr[2][4];
            int s16 = kt * 2 + (lane >> 4);
#pragma unroll
            for (int mt = 0; mt < 2; ++mt) {
                int row = wm * 32 + mt * 16 + (lane & 15);
                ldsm4(af[mt], sA + row * 128 + ((s16 ^ (row & 7)) << 4));
            }
#pragma unroll
            for (int g = 0; g < 2; ++g) {
                int row = wn * 32 + g * 16 + (lane & 15);
                ldsm4(bfr[g], sB + row * 128 + ((s16 ^ (row & 7)) << 4));
            }
#pragma unroll
            for (int mt = 0; mt < 2; ++mt)
#pragma unroll
                for (int nt = 0; nt < 4; ++nt)
                    mma_bf16(acc[mt][nt], af[mt],
                             bfr[nt >> 1][nt & 1], bfr[nt >> 1][(nt & 1) + 2]);
        }
    }
    CP_WAIT(0);
    __syncthreads();

    const int r0 = wm * 32 + (lane >> 2);
    const int c0 = wn * 32 + 2 * (lane & 3);
    bf16* st = (bf16*)(smem_raw + (sb - smem_u32(smem_raw)));
#pragma unroll
    for (int mt = 0; mt < 2; ++mt)
#pragma unroll
        for (int nt = 0; nt < 4; ++nt) {
            int r = r0 + mt * 16, c = c0 + nt * 8;
            *(__nv_bfloat162*)&st[r * 72 + c] =
                __floats2bfloat162_rn(acc[mt][nt][0], acc[mt][nt][1]);
            *(__nv_bfloat162*)&st[(r + 8) * 72 + c] =
                __floats2bfloat162_rn(acc[mt][nt][2], acc[mt][nt][3]);
        }
    __syncthreads();
    bf16* dst = g_At + ((size_t)b * HW + m0) * MID;
#pragma unroll
    for (int u = 0; u < 8; ++u) {
        int idx = tid + u * 256;
        int row = idx >> 4, ch = idx & 15;
        uint2 v = *(uint2*)&st[row * 72 + ch * 4];
        *(uint2*)&dst[(size_t)row * MID + ch * 4] = v;
    }
}

// ---------------------------------------------------------------------------
// Fused prep: keymid (blocks 0..4095) + wconv (4096..4351) + wmix (4352..4415)
// ---------------------------------------------------------------------------
__global__ void prep_kernel(const float* __restrict__ bmap,
                            const float* __restrict__ w1,
                            const float* __restrict__ bs,
                            const float* __restrict__ bbias,
                            const float* __restrict__ bmean,
                            const float* __restrict__ bvar,
                            const float* __restrict__ qw,
                            const float* __restrict__ vw,
                            const float* __restrict__ kw2)
{
    int blk = blockIdx.x, tid = threadIdx.x;
    if (blk < 4096) {               // keymid: Tt[b][p][m]
        int idx = blk * 256 + tid;
        int m = idx & 63, p = (idx >> 6) & (HW - 1), b = idx >> 18;
        float inv = bs[m] * rsqrtf(bvar[m] + 1e-5f);
        float a   = w1[m] * inv;
        float bb  = bbias[m] - bmean[m] * inv;
        int y = p >> 6, x = p & 63;
        float s = bmap[b * 16384 + y * 256 + x * 2];
        g_Tt[idx] = __float2bfloat16(fmaxf(fmaf(a, s, bb), 0.0f));
    } else if (blk < 4352) {        // wconv: Wv bf16
        int i = (blk - 4096) * 256 + tid;
        g_Wv[i] = __float2bfloat16(vw[i]);
    } else {                        // wmix: Mt[m][c] = sum_o Wq[o][c] Wk2[o][m]
        int m = blk - 4352, c = tid;
        float acc = 0.0f;
#pragma unroll 8
        for (int o = 0; o < CCH; ++o)
            acc += qw[o * CCH + c] * kw2[o * MID + m];
        g_Mt[m * CCH + c] = __float2bfloat16(acc);
    }
}

__global__ void transU_kernel(const float* __restrict__ U) {
    __shared__ float t[32][33];
    int b = blockIdx.z, c0 = blockIdx.y * 32, j0 = blockIdx.x * 32;
    int tx = threadIdx.x, ty = threadIdx.y;
    const float* Ub = U + ((size_t)b * CCH + c0) * HW + j0;
#pragma unroll
    for (int k = 0; k < 4; ++k)
        t[ty + 8 * k][tx] = Ub[(size_t)(ty + 8 * k) * HW + tx];
    __syncthreads();
    bf16* Utb = g_Ut + ((size_t)b * HW + j0) * CCH + c0;
#pragma unroll
    for (int k = 0; k < 4; ++k)
        Utb[(size_t)(ty + 8 * k) * CCH + tx] = __float2bfloat16(t[tx][ty + 8 * k]);
}

__global__ void zinv_kernel() {
    int t = blockIdx.x * 256 + threadIdx.x;     // BATCH*HW
    int b = t >> 12, i = t & (HW - 1);
    float s = 0.0f;
#pragma unroll
    for (int p = 0; p < 32; ++p)
        s += g_Zp[((size_t)b * 32 + p) * HW + i];
    g_Zi[t] = 4096.0f / s;       // 4096 scale folded here (undone by gamma/4096)
}

// ---------------------------------------------------------------------------
extern "C" void kernel_launch(void* const* d_in, const int* in_sizes, int n_in,
                              void* d_out, int out_size)
{
    const float* bmap     = (const float*)d_in[0];
    const float* U        = (const float*)d_in[1];
    const float* key_w1   = (const float*)d_in[2];
    const float* bn_scale = (const float*)d_in[3];
    const float* bn_bias  = (const float*)d_in[4];
    const float* bn_mean  = (const float*)d_in[5];
    const float* bn_var   = (const float*)d_in[6];
    const float* key_w2   = (const float*)d_in[7];
    const float* query_w  = (const float*)d_in[8];
    const float* value_w  = (const float*)d_in[9];
    const float* gamma    = (const float*)d_in[10];
    float* out = (float*)d_out;

    cudaFuncSetAttribute(gemm_hmma<2>, cudaFuncAttributeMaxDynamicSharedMemorySize, SMEM_SM);
    cudaFuncSetAttribute(gemm_hmma<3>, cudaFuncAttributeMaxDynamicSharedMemorySize, SMEM_SM);
    cudaFuncSetAttribute(gemm_hmma<4>, cudaFuncAttributeMaxDynamicSharedMemorySize, SMEM_SM);
    cudaFuncSetAttribute(gemm_at,      cudaFuncAttributeMaxDynamicSharedMemorySize, SMEM_AT);

    // 1) fused prep (Tt, Wv-bf16, Mt)
    prep_kernel<<<4416, 256>>>(bmap, key_w1, bn_scale, bn_bias, bn_mean, bn_var,
                               query_w, value_w, key_w2);
    // 2) Ut[b][j][c]
    transU_kernel<<<dim3(HW / 32, CCH / 32, BATCH), dim3(32, 8)>>>(U);
    // 3) A'[j][m] = Ut . Mt^T
    gemm_at<<<dim3(1, 32, BATCH), 256, SMEM_AT>>>();
    // 4) S8[j][i] = e4m3(exp(A'_j . T_i)) + reduced Z partials   (K=64)  [profiled]
    gemm_hmma<2><<<dim3(32, 32, BATCH), 256, SMEM_SM>>>(U, gamma, out);
    // 5) Zi = 4096/Z
    zinv_kernel<<<(BATCH * HW) / 256, 256>>>();
    // 6) Vz8[c][i] = e4m3((Wv @ U)[c][i] * 4096/Z[i])
    gemm_hmma<3><<<dim3(32, 2, BATCH), 256, SMEM_SM>>>(U, gamma, out);
    // 7) out[c][j] = gamma/4096 * sum_i Vz8[c][i] S8[j][i] + U[c][j]   (fp8)
    gemm_hmma<4><<<dim3(32, 2, BATCH), 256, SMEM_SM>>>(U, gamma, out);
}

// round 14
// speedup vs baseline: 1.2039x; 1.0206x over previous
#include <cuda_runtime.h>
#include <cuda_bf16.h>
#include <cuda_fp16.h>
#include <cstdint>

#define BATCH 4
#define CCH   256
#define HW    4096
#define MID   64

using bf16 = __nv_bfloat16;

// ---------------- device-global scratch (allocation-free rule) --------------
__device__ __align__(1024) bf16 g_Ut[(size_t)BATCH * HW * CCH];   // [b][j][c]
__device__ __align__(1024) bf16 g_Tt[(size_t)BATCH * HW * MID];   // [b][i][m]
__device__ __align__(1024) bf16 g_Mt[MID * CCH];                  // [m][c]  Wq^T Wk2
__device__ __align__(1024) bf16 g_Wv[CCH * CCH];
__device__ __align__(1024) bf16 g_At[(size_t)BATCH * HW * MID];   // [b][j][m] (x log2e)
__device__ __align__(1024) uint8_t g_Vz8[(size_t)BATCH * CCH * HW]; // [b][c][i] e4m3
__device__ __align__(1024) uint8_t g_S8 [(size_t)BATCH * HW * HW];  // [b][j][i] e4m3 64MB
__device__ float g_Zp[(size_t)BATCH * 32 * HW];                   // 2MB partials
__device__ float g_Zi[BATCH * HW];                                // 4096/Z

// ---------------- PTX helpers ----------------------------------------------
__device__ __forceinline__ uint32_t smem_u32(const void* p) {
    uint32_t a;
    asm("{ .reg .u64 t; cvta.to.shared.u64 t, %1; cvt.u32.u64 %0, t; }"
        : "=r"(a) : "l"(p));
    return a;
}
__device__ __forceinline__ void cp16(uint32_t s, const void* g) {
    asm volatile("cp.async.cg.shared.global [%0], [%1], 16;" :: "r"(s), "l"(g));
}
#define CP_COMMIT() asm volatile("cp.async.commit_group;" ::: "memory")
#define CP_WAIT(n)  asm volatile("cp.async.wait_group %0;" :: "n"(n) : "memory")

__device__ __forceinline__ void ldsm4(uint32_t* r, uint32_t a) {
    asm volatile("ldmatrix.sync.aligned.m8n8.x4.shared.b16 {%0,%1,%2,%3}, [%4];"
                 : "=r"(r[0]), "=r"(r[1]), "=r"(r[2]), "=r"(r[3]) : "r"(a));
}
__device__ __forceinline__ void mma_bf16(float* d, const uint32_t* a,
                                         uint32_t b0, uint32_t b1) {
    asm volatile("mma.sync.aligned.m16n8k16.row.col.f32.bf16.bf16.f32 "
                 "{%0,%1,%2,%3}, {%4,%5,%6,%7}, {%8,%9}, {%0,%1,%2,%3};"
                 : "+f"(d[0]), "+f"(d[1]), "+f"(d[2]), "+f"(d[3])
                 : "r"(a[0]), "r"(a[1]), "r"(a[2]), "r"(a[3]), "r"(b0), "r"(b1));
}
__device__ __forceinline__ void mma_fp8(float* d, const uint32_t* a,
                                        uint32_t b0, uint32_t b1) {
    asm volatile("mma.sync.aligned.m16n8k32.row.col.f32.e4m3.e4m3.f32 "
                 "{%0,%1,%2,%3}, {%4,%5,%6,%7}, {%8,%9}, {%0,%1,%2,%3};"
                 : "+f"(d[0]), "+f"(d[1]), "+f"(d[2]), "+f"(d[3])
                 : "r"(a[0]), "r"(a[1]), "r"(a[2]), "r"(a[3]), "r"(b0), "r"(b1));
}
// pack 2 floats -> e4m3x2 (b16 dest; low byte = f0)
__device__ __forceinline__ uint16_t pack2_e4m3(float f0, float f1) {
    uint16_t v;
    asm("cvt.rn.satfinite.e4m3x2.f32 %0, %1, %2;" : "=h"(v) : "f"(f1), "f"(f0));
    return v;
}
__device__ __forceinline__ uint32_t pack4_e4m3(float f0, float f1, float f2, float f3) {
    uint32_t lo = pack2_e4m3(f0, f1), hi = pack2_e4m3(f2, f3);
    return (hi << 16) | lo;
}
// 2^x fast
__device__ __forceinline__ float ex2f(float x) {
    float y;
    asm("ex2.approx.ftz.f32 %0, %1;" : "=f"(y) : "f"(x));
    return y;
}

#define EPI_STRIDE  136   // fp32 staging stride (elems)
#define S8_STRIDE   132   // fp8 staging stride (bytes)
#define ZSM_OFF     20480 // Z reduction scratch (beyond 128*132 S8 staging)

// ---- main kernel smem: 3 stages x (A 16KB + B 16KB) ----
#define STAGE_SM  32768
#define SMEM_SM   (3 * STAGE_SM + 128)
// ---- A' kernel smem: 3 stages x (A 16KB + B 8KB) ----
#define STAGE_AT  24576
#define SMEM_AT   (3 * STAGE_AT + 128)

// load nrows x 128B rows, SW128 swizzle, 256 threads
template<int NROWS>
__device__ __forceinline__ void ldtile(uint32_t sbuf, const char* g,
                                       size_t stride, int tid) {
#pragma unroll
    for (int u = 0; u < NROWS / 32; ++u) {
        int idx = tid + u * 256;
        int r = idx >> 3, s = idx & 7;
        cp16(sbuf + r * 128 + ((s ^ (r & 7)) << 4), g + (size_t)r * stride + (s << 4));
    }
}

// ---------------------------------------------------------------------------
// HMMA GEMM (256 thr, 2 CTA/SM, 64x32 warp tiles): D[128x128] = A * B^T
// MODE 2 (bf16): S  A=At(j)  B=Tt(i)  K=64el  -> S8[j][i]=e4m3(2^E), Zp
// MODE 3 (bf16): Vz A=Wv(c)  B=Ut(i)  K=256el -> Vz8[c][i] = e4m3(V*4096/Z)
// MODE 4 (fp8):  Out A=Vz8(c) B=S8(j) K=4096el-> out=gamma/4096*x+U
// ---------------------------------------------------------------------------
template<int MODE>
__global__ void __launch_bounds__(256, 2) gemm_hmma(const float* __restrict__ U,
                                                    const float* __restrict__ gammap,
                                                    float* __restrict__ Out)
{
    extern __shared__ char smem_raw[];
    uint32_t sb = (smem_u32(smem_raw) + 127u) & ~127u;
    const int tid = threadIdx.x, lane = tid & 31, wid = tid >> 5;
    const int wm = wid & 1, wn = wid >> 1;
    const int b = blockIdx.z;
    const int m0 = blockIdx.y * 128, n0 = blockIdx.x * 128;

    constexpr int NC = (MODE == 2) ? 1 : (MODE == 3 ? 4 : 32);

    const char *gA, *gB;
    size_t strA, strB;
    if (MODE == 2) {
        gA = (const char*)(g_At + ((size_t)b * HW + m0) * MID); strA = MID * 2;
        gB = (const char*)(g_Tt + ((size_t)b * HW + n0) * MID); strB = MID * 2;
    } else if (MODE == 3) {
        gA = (const char*)(g_Wv + (size_t)m0 * CCH);            strA = CCH * 2;
        gB = (const char*)(g_Ut + ((size_t)b * HW + n0) * CCH); strB = CCH * 2;
    } else {
        gA = (const char*)(g_Vz8 + (size_t)b * CCH * HW + (size_t)m0 * HW); strA = HW;
        gB = (const char*)(g_S8 + (size_t)b * HW * HW + (size_t)n0 * HW);   strB = HW;
    }

    float acc[4][4][4] = {};

    ldtile<128>(sb, gA, strA, tid);
    ldtile<128>(sb + 16384, gB, strB, tid);
    CP_COMMIT();
    if (NC > 1) {
        ldtile<128>(sb + STAGE_SM, gA + 128, strA, tid);
        ldtile<128>(sb + STAGE_SM + 16384, gB + 128, strB, tid);
    }
    CP_COMMIT();

#pragma unroll 1
    for (int n = 0; n < NC; ++n) {
        CP_WAIT(1);
        __syncthreads();
        if (n + 2 < NC) {
            uint32_t sp = sb + ((n + 2) % 3) * STAGE_SM;
            ldtile<128>(sp, gA + (size_t)(n + 2) * 128, strA, tid);
            ldtile<128>(sp + 16384, gB + (size_t)(n + 2) * 128, strB, tid);
        }
        CP_COMMIT();

        uint32_t sA = sb + (n % 3) * STAGE_SM;
        uint32_t sB = sA + 16384;
#pragma unroll
        for (int kt = 0; kt < 4; ++kt) {
            uint32_t af[4][4], bfr[2][4];
            int s16 = kt * 2 + (lane >> 4);
#pragma unroll
            for (int mt = 0; mt < 4; ++mt) {
                int row = wm * 64 + mt * 16 + (lane & 15);
                ldsm4(af[mt], sA + row * 128 + ((s16 ^ (row & 7)) << 4));
            }
#pragma unroll
            for (int g = 0; g < 2; ++g) {
                int row = wn * 32 + g * 16 + (lane & 15);
                ldsm4(bfr[g], sB + row * 128 + ((s16 ^ (row & 7)) << 4));
            }
#pragma unroll
            for (int mt = 0; mt < 4; ++mt)
#pragma unroll
                for (int nt = 0; nt < 4; ++nt) {
                    if (MODE == 4)
                        mma_fp8(acc[mt][nt], af[mt],
                                bfr[nt >> 1][nt & 1], bfr[nt >> 1][(nt & 1) + 2]);
                    else
                        mma_bf16(acc[mt][nt], af[mt],
                                 bfr[nt >> 1][nt & 1], bfr[nt >> 1][(nt & 1) + 2]);
                }
        }
    }
    CP_WAIT(0);
    __syncthreads();

    const int r0 = wm * 64 + (lane >> 2);
    const int c0 = wn * 32 + 2 * (lane & 3);

    if (MODE == 2) {
        // 2^E -> e4m3 staging; Z accumulated from pre-rounding floats in regs
        char* smem_base = smem_raw + (sb - smem_u32(smem_raw));
        uint8_t* st8 = (uint8_t*)smem_base;
        float zc[8] = {0, 0, 0, 0, 0, 0, 0, 0};   // cols c0+nt*8+{0,1}
#pragma unroll
        for (int mt = 0; mt < 4; ++mt)
#pragma unroll
            for (int nt = 0; nt < 4; ++nt) {
                float v0 = ex2f(acc[mt][nt][0]), v1 = ex2f(acc[mt][nt][1]);
                float v2 = ex2f(acc[mt][nt][2]), v3 = ex2f(acc[mt][nt][3]);
                zc[nt * 2 + 0] += v0 + v2;
                zc[nt * 2 + 1] += v1 + v3;
                int r = r0 + mt * 16, c = c0 + nt * 8;
                *(uint16_t*)&st8[r * S8_STRIDE + c] = pack2_e4m3(v0, v1);
                *(uint16_t*)&st8[(r + 8) * S8_STRIDE + c] = pack2_e4m3(v2, v3);
            }
        // reduce over the 8 row-lanes (lane bits 2..4); deterministic order
#pragma unroll
        for (int off = 4; off <= 16; off <<= 1)
#pragma unroll
            for (int k = 0; k < 8; ++k)
                zc[k] += __shfl_xor_sync(0xffffffffu, zc[k], off);
        float* zsm = (float*)(smem_base + ZSM_OFF);   // [2][128]
        if ((lane >> 2) == 0) {
#pragma unroll
            for (int nt = 0; nt < 4; ++nt) {
                int col = wn * 32 + 2 * (lane & 3) + nt * 8;
                zsm[wm * 128 + col]     = zc[nt * 2 + 0];
                zsm[wm * 128 + col + 1] = zc[nt * 2 + 1];
            }
        }
        __syncthreads();
        // pure copy smem -> gmem (coalesced)
        uint8_t* Sp = g_S8 + (size_t)b * HW * HW;
        int ch = tid & 31, h = tid >> 5;
#pragma unroll
        for (int r = 0; r < 16; ++r) {
            int row = h * 16 + r;
            *(uint32_t*)&Sp[(size_t)(m0 + row) * HW + n0 + ch * 4] =
                *(uint32_t*)&st8[row * S8_STRIDE + ch * 4];
        }
        if (tid < 128)
            g_Zp[((size_t)b * 32 + blockIdx.y) * HW + n0 + tid] =
                zsm[tid] + zsm[128 + tid];
    } else if (MODE == 3) {
        float* st = (float*)(smem_raw + (sb - smem_u32(smem_raw)));
#pragma unroll
        for (int mt = 0; mt < 4; ++mt)
#pragma unroll
            for (int nt = 0; nt < 4; ++nt) {
                int r = r0 + mt * 16, c = c0 + nt * 8;
                *(float2*)&st[r * EPI_STRIDE + c] = make_float2(acc[mt][nt][0], acc[mt][nt][1]);
                *(float2*)&st[(r + 8) * EPI_STRIDE + c] = make_float2(acc[mt][nt][2], acc[mt][nt][3]);
            }
        __syncthreads();
#pragma unroll
        for (int u = 0; u < 16; ++u) {
            int idx = tid + u * 256;
            int row = idx >> 5, ch = idx & 31;
            float4 v = *(float4*)&st[row * EPI_STRIDE + ch * 4];
            float4 z = *(const float4*)&g_Zi[b * HW + n0 + ch * 4];   // = 4096/Z
            uint32_t p = pack4_e4m3(v.x * z.x, v.y * z.y, v.z * z.z, v.w * z.w);
            *(uint32_t*)&g_Vz8[((size_t)b * CCH + m0 + row) * HW + n0 + ch * 4] = p;
        }
    } else {  // MODE 4
        float* st = (float*)(smem_raw + (sb - smem_u32(smem_raw)));
        float gamma = __ldg(gammap) * (1.0f / 4096.0f);
#pragma unroll
        for (int mt = 0; mt < 4; ++mt)
#pragma unroll
            for (int nt = 0; nt < 4; ++nt) {
                int r = r0 + mt * 16, c = c0 + nt * 8;
                *(float2*)&st[r * EPI_STRIDE + c] = make_float2(acc[mt][nt][0], acc[mt][nt][1]);
                *(float2*)&st[(r + 8) * EPI_STRIDE + c] = make_float2(acc[mt][nt][2], acc[mt][nt][3]);
            }
        __syncthreads();
#pragma unroll
        for (int u = 0; u < 16; ++u) {
            int idx = tid + u * 256;
            int row = idx >> 5, ch = idx & 31;
            float4 v = *(float4*)&st[row * EPI_STRIDE + ch * 4];
            size_t off = ((size_t)b * CCH + m0 + row) * HW + n0 + ch * 4;
            float4 uv = *(const float4*)(U + off);
            float4 o;
            o.x = fmaf(gamma, v.x, uv.x); o.y = fmaf(gamma, v.y, uv.y);
            o.z = fmaf(gamma, v.z, uv.z); o.w = fmaf(gamma, v.w, uv.w);
            *(float4*)(Out + off) = o;
        }
    }
}

// ---------------------------------------------------------------------------
// A' GEMM: D[128 x 64] = Ut(128 j-rows, K=256) * Mt(64 m-rows, K=256)^T
// Epilogue scales by log2e so mode-2 can use bare ex2.
// ---------------------------------------------------------------------------
__global__ void __launch_bounds__(256, 2) gemm_at()
{
    extern __shared__ char smem_raw[];
    uint32_t sb = (smem_u32(smem_raw) + 127u) & ~127u;
    const int tid = threadIdx.x, lane = tid & 31, wid = tid >> 5;
    const int wm = wid >> 1, wn = wid & 1;
    const int b = blockIdx.z;
    const int m0 = blockIdx.y * 128;

    constexpr int NC = CCH / 64;   // 4
    const char* gA = (const char*)(g_Ut + ((size_t)b * HW + m0) * CCH);
    const char* gB = (const char*)g_Mt;
    const size_t strA = CCH * 2, strB = CCH * 2;

    float acc[2][4][4] = {};

    ldtile<128>(sb, gA, strA, tid);
    ldtile<64>(sb + 16384, gB, strB, tid);
    CP_COMMIT();
    ldtile<128>(sb + STAGE_AT, gA + 128, strA, tid);
    ldtile<64>(sb + STAGE_AT + 16384, gB + 128, strB, tid);
    CP_COMMIT();

#pragma unroll 1
    for (int n = 0; n < NC; ++n) {
        CP_WAIT(1);
        __syncthreads();
        if (n + 2 < NC) {
            uint32_t sp = sb + ((n + 2) % 3) * STAGE_AT;
            ldtile<128>(sp, gA + (size_t)(n + 2) * 128, strA, tid);
            ldtile<64>(sp + 16384, gB + (size_t)(n + 2) * 128, strB, tid);
        }
        CP_COMMIT();

        uint32_t sA = sb + (n % 3) * STAGE_AT;
        uint32_t sB = sA + 16384;
#pragma unroll
        for (int kt = 0; kt < 4; ++kt) {
            uint32_t af[2][4], bfr[2][4];
            int s16 = kt * 2 + (lane >> 4);
#pragma unroll
            for (int mt = 0; mt < 2; ++mt) {
                int row = wm * 32 + mt * 16 + (lane & 15);
                ldsm4(af[mt], sA + row * 128 + ((s16 ^ (row & 7)) << 4));
            }
#pragma unroll
            for (int g = 0; g < 2; ++g) {
                int row = wn * 32 + g * 16 + (lane & 15);
                ldsm4(bfr[g], sB + row * 128 + ((s16 ^ (row & 7)) << 4));
            }
#pragma unroll
            for (int mt = 0; mt < 2; ++mt)
#pragma unroll
                for (int nt = 0; nt < 4; ++nt)
                    mma_bf16(acc[mt][nt], af[mt],
                             bfr[nt >> 1][nt & 1], bfr[nt >> 1][(nt & 1) + 2]);
        }
    }
    CP_WAIT(0);
    __syncthreads();

    const float LOG2E = 1.4426950408889634f;
    const int r0 = wm * 32 + (lane >> 2);
    const int c0 = wn * 32 + 2 * (lane & 3);
    bf16* st = (bf16*)(smem_raw + (sb - smem_u32(smem_raw)));
#pragma unroll
    for (int mt = 0; mt < 2; ++mt)
#pragma unroll
        for (int nt = 0; nt < 4; ++nt) {
            int r = r0 + mt * 16, c = c0 + nt * 8;
            *(__nv_bfloat162*)&st[r * 72 + c] =
                __floats2bfloat162_rn(acc[mt][nt][0] * LOG2E, acc[mt][nt][1] * LOG2E);
            *(__nv_bfloat162*)&st[(r + 8) * 72 + c] =
                __floats2bfloat162_rn(acc[mt][nt][2] * LOG2E, acc[mt][nt][3] * LOG2E);
        }
    __syncthreads();
    bf16* dst = g_At + ((size_t)b * HW + m0) * MID;
#pragma unroll
    for (int u = 0; u < 8; ++u) {
        int idx = tid + u * 256;
        int row = idx >> 4, ch = idx & 15;
        uint2 v = *(uint2*)&st[row * 72 + ch * 4];
        *(uint2*)&dst[(size_t)row * MID + ch * 4] = v;
    }
}

// ---------------------------------------------------------------------------
// Fused prep: keymid (blocks 0..4095) + wconv (4096..4351) + wmix (4352..4415)
// ---------------------------------------------------------------------------
__global__ void prep_kernel(const float* __restrict__ bmap,
                            const float* __restrict__ w1,
                            const float* __restrict__ bs,
                            const float* __restrict__ bbias,
                            const float* __restrict__ bmean,
                            const float* __restrict__ bvar,
                            const float* __restrict__ qw,
                            const float* __restrict__ vw,
                            const float* __restrict__ kw2)
{
    int blk = blockIdx.x, tid = threadIdx.x;
    if (blk < 4096) {               // keymid: Tt[b][p][m]
        int idx = blk * 256 + tid;
        int m = idx & 63, p = (idx >> 6) & (HW - 1), b = idx >> 18;
        float inv = bs[m] * rsqrtf(bvar[m] + 1e-5f);
        float a   = w1[m] * inv;
        float bb  = bbias[m] - bmean[m] * inv;
        int y = p >> 6, x = p & 63;
        float s = bmap[b * 16384 + y * 256 + x * 2];
        g_Tt[idx] = __float2bfloat16(fmaxf(fmaf(a, s, bb), 0.0f));
    } else if (blk < 4352) {        // wconv: Wv bf16
        int i = (blk - 4096) * 256 + tid;
        g_Wv[i] = __float2bfloat16(vw[i]);
    } else {                        // wmix: Mt[m][c] = sum_o Wq[o][c] Wk2[o][m]
        int m = blk - 4352, c = tid;
        float acc = 0.0f;
#pragma unroll 8
        for (int o = 0; o < CCH; ++o)
            acc += qw[o * CCH + c] * kw2[o * MID + m];
        g_Mt[m * CCH + c] = __float2bfloat16(acc);
    }
}

__global__ void transU_kernel(const float* __restrict__ U) {
    __shared__ float t[32][33];
    int b = blockIdx.z, c0 = blockIdx.y * 32, j0 = blockIdx.x * 32;
    int tx = threadIdx.x, ty = threadIdx.y;
    const float* Ub = U + ((size_t)b * CCH + c0) * HW + j0;
#pragma unroll
    for (int k = 0; k < 4; ++k)
        t[ty + 8 * k][tx] = Ub[(size_t)(ty + 8 * k) * HW + tx];
    __syncthreads();
    bf16* Utb = g_Ut + ((size_t)b * HW + j0) * CCH + c0;
#pragma unroll
    for (int k = 0; k < 4; ++k)
        Utb[(size_t)(ty + 8 * k) * CCH + tx] = __float2bfloat16(t[tx][ty + 8 * k]);
}

__global__ void zinv_kernel() {
    int t = blockIdx.x * 256 + threadIdx.x;     // BATCH*HW
    int b = t >> 12, i = t & (HW - 1);
    float s = 0.0f;
#pragma unroll
    for (int p = 0; p < 32; ++p)
        s += g_Zp[((size_t)b * 32 + p) * HW + i];
    g_Zi[t] = 4096.0f / s;       // 4096 scale folded here (undone by gamma/4096)
}

// ---------------------------------------------------------------------------
extern "C" void kernel_launch(void* const* d_in, const int* in_sizes, int n_in,
                              void* d_out, int out_size)
{
    const float* bmap     = (const float*)d_in[0];
    const float* U        = (const float*)d_in[1];
    const float* key_w1   = (const float*)d_in[2];
    const float* bn_scale = (const float*)d_in[3];
    const float* bn_bias  = (const float*)d_in[4];
    const float* bn_mean  = (const float*)d_in[5];
    const float* bn_var   = (const float*)d_in[6];
    const float* key_w2   = (const float*)d_in[7];
    const float* query_w  = (const float*)d_in[8];
    const float* value_w  = (const float*)d_in[9];
    const float* gamma    = (const float*)d_in[10];
    float* out = (float*)d_out;

    cudaFuncSetAttribute(gemm_hmma<2>, cudaFuncAttributeMaxDynamicSharedMemorySize, SMEM_SM);
    cudaFuncSetAttribute(gemm_hmma<3>, cudaFuncAttributeMaxDynamicSharedMemorySize, SMEM_SM);
    cudaFuncSetAttribute(gemm_hmma<4>, cudaFuncAttributeMaxDynamicSharedMemorySize, SMEM_SM);
    cudaFuncSetAttribute(gemm_at,      cudaFuncAttributeMaxDynamicSharedMemorySize, SMEM_AT);

    // 1) fused prep (Tt, Wv-bf16, Mt)
    prep_kernel<<<4416, 256>>>(bmap, key_w1, bn_scale, bn_bias, bn_mean, bn_var,
                               query_w, value_w, key_w2);
    // 2) Ut[b][j][c]
    transU_kernel<<<dim3(HW / 32, CCH / 32, BATCH), dim3(32, 8)>>>(U);
    // 3) A'[j][m] = (Ut . Mt^T) * log2e
    gemm_at<<<dim3(1, 32, BATCH), 256, SMEM_AT>>>();
    // 4) S8[j][i] = e4m3(2^(A'_j . T_i)) + reduced Z partials   (K=64)  [profiled]
    gemm_hmma<2><<<dim3(32, 32, BATCH), 256, SMEM_SM>>>(U, gamma, out);
    // 5) Zi = 4096/Z
    zinv_kernel<<<(BATCH * HW) / 256, 256>>>();
    // 6) Vz8[c][i] = e4m3((Wv @ U)[c][i] * 4096/Z[i])
    gemm_hmma<3><<<dim3(32, 2, BATCH), 256, SMEM_SM>>>(U, gamma, out);
    // 7) out[c][j] = gamma/4096 * sum_i Vz8[c][i] S8[j][i] + U[c][j]   (fp8)
    gemm_hmma<4><<<dim3(32, 2, BATCH), 256, SMEM_SM>>>(U, gamma, out);
}

// round 15
// speedup vs baseline: 1.2275x; 1.0196x over previous
#include <cuda_runtime.h>
#include <cuda_bf16.h>
#include <cuda_fp16.h>
#include <cstdint>

#define BATCH 4
#define CCH   256
#define HW    4096
#define MID   64

using bf16 = __nv_bfloat16;

// ---------------- device-global scratch (allocation-free rule) --------------
__device__ __align__(1024) bf16 g_Ut[(size_t)BATCH * HW * CCH];   // [b][j][c]
__device__ __align__(1024) bf16 g_Tt[(size_t)BATCH * HW * MID];   // [b][i][m]
__device__ __align__(1024) bf16 g_Mt[MID * CCH];                  // [m][c]  Wq^T Wk2
__device__ __align__(1024) bf16 g_Wv[CCH * CCH];
__device__ __align__(1024) bf16 g_At[(size_t)BATCH * HW * MID];   // [b][j][m] (x log2e)
__device__ __align__(1024) uint8_t g_Vz8[(size_t)BATCH * CCH * HW]; // [b][c][i] e4m3
__device__ __align__(1024) uint8_t g_S8 [(size_t)BATCH * HW * HW];  // [b][j][i] e4m3 64MB
__device__ float g_Zp[(size_t)BATCH * 32 * HW];                   // 2MB partials
__device__ float g_Zi[BATCH * HW];                                // 4096/Z

// ---------------- PTX helpers ----------------------------------------------
__device__ __forceinline__ uint32_t smem_u32(const void* p) {
    uint32_t a;
    asm("{ .reg .u64 t; cvta.to.shared.u64 t, %1; cvt.u32.u64 %0, t; }"
        : "=r"(a) : "l"(p));
    return a;
}
__device__ __forceinline__ void cp16(uint32_t s, const void* g) {
    asm volatile("cp.async.cg.shared.global [%0], [%1], 16;" :: "r"(s), "l"(g));
}
#define CP_COMMIT() asm volatile("cp.async.commit_group;" ::: "memory")
#define CP_WAIT(n)  asm volatile("cp.async.wait_group %0;" :: "n"(n) : "memory")

__device__ __forceinline__ void ldsm4(uint32_t* r, uint32_t a) {
    asm volatile("ldmatrix.sync.aligned.m8n8.x4.shared.b16 {%0,%1,%2,%3}, [%4];"
                 : "=r"(r[0]), "=r"(r[1]), "=r"(r[2]), "=r"(r[3]) : "r"(a));
}
__device__ __forceinline__ void mma_bf16(float* d, const uint32_t* a,
                                         uint32_t b0, uint32_t b1) {
    asm volatile("mma.sync.aligned.m16n8k16.row.col.f32.bf16.bf16.f32 "
                 "{%0,%1,%2,%3}, {%4,%5,%6,%7}, {%8,%9}, {%0,%1,%2,%3};"
                 : "+f"(d[0]), "+f"(d[1]), "+f"(d[2]), "+f"(d[3])
                 : "r"(a[0]), "r"(a[1]), "r"(a[2]), "r"(a[3]), "r"(b0), "r"(b1));
}
__device__ __forceinline__ void mma_fp8(float* d, const uint32_t* a,
                                        uint32_t b0, uint32_t b1) {
    asm volatile("mma.sync.aligned.m16n8k32.row.col.f32.e4m3.e4m3.f32 "
                 "{%0,%1,%2,%3}, {%4,%5,%6,%7}, {%8,%9}, {%0,%1,%2,%3};"
                 : "+f"(d[0]), "+f"(d[1]), "+f"(d[2]), "+f"(d[3])
                 : "r"(a[0]), "r"(a[1]), "r"(a[2]), "r"(a[3]), "r"(b0), "r"(b1));
}
// pack 2 floats -> e4m3x2 (b16 dest; low byte = f0)
__device__ __forceinline__ uint16_t pack2_e4m3(float f0, float f1) {
    uint16_t v;
    asm("cvt.rn.satfinite.e4m3x2.f32 %0, %1, %2;" : "=h"(v) : "f"(f1), "f"(f0));
    return v;
}
__device__ __forceinline__ uint32_t pack4_e4m3(float f0, float f1, float f2, float f3) {
    uint32_t lo = pack2_e4m3(f0, f1), hi = pack2_e4m3(f2, f3);
    return (hi << 16) | lo;
}
// 2^x fast
__device__ __forceinline__ float ex2f(float x) {
    float y;
    asm("ex2.approx.ftz.f32 %0, %1;" : "=f"(y) : "f"(x));
    return y;
}

#define EPI_STRIDE  136   // fp32 staging stride (elems)
#define S8_STRIDE   132   // fp8 staging stride (bytes)

// ---- mode3/4 kernel smem: 3 stages x (A 16KB + B 16KB) ----
#define STAGE_SM  32768
#define SMEM_SM   (3 * STAGE_SM + 128)
// ---- mode2 kernel smem: A 16KB + 3 B stages 48KB + staging 20KB + zsm 1KB ----
#define S2_EPI    65536
#define S2_ZSM    86016
#define SMEM_S2   (86016 + 1024 + 128)
// ---- A' kernel smem: 3 stages x (A 16KB + B 8KB) ----
#define STAGE_AT  24576
#define SMEM_AT   (3 * STAGE_AT + 128)

// load nrows x 128B rows, SW128 swizzle, 256 threads
template<int NROWS>
__device__ __forceinline__ void ldtile(uint32_t sbuf, const char* g,
                                       size_t stride, int tid) {
#pragma unroll
    for (int u = 0; u < NROWS / 32; ++u) {
        int idx = tid + u * 256;
        int r = idx >> 3, s = idx & 7;
        cp16(sbuf + r * 128 + ((s ^ (r & 7)) << 4), g + (size_t)r * stride + (s << 4));
    }
}

// ---------------------------------------------------------------------------
// Mode-2 kernel: per CTA computes S8[j-tile 128][i-range 512] in 4 i-tiles.
// A (At j-tile, K=64, x log2e) resident; B (Tt i-tiles) 3-stage pipelined.
// Epilogue per i-tile: 2^E -> e4m3 -> S8 store + Z partials.
// ---------------------------------------------------------------------------
__global__ void __launch_bounds__(256, 2) gemm_s()
{
    extern __shared__ char smem_raw[];
    uint32_t sb = (smem_u32(smem_raw) + 127u) & ~127u;
    const int tid = threadIdx.x, lane = tid & 31, wid = tid >> 5;
    const int wm = wid & 1, wn = wid >> 1;
    const int b = blockIdx.z;
    const int m0 = blockIdx.y * 128;
    const int i0 = blockIdx.x * 512;

    const char* gA = (const char*)(g_At + ((size_t)b * HW + m0) * MID);
    const char* gB = (const char*)(g_Tt + ((size_t)b * HW + i0) * MID);

    // prologue: A + B0, then B1
    ldtile<128>(sb, gA, 128, tid);
    ldtile<128>(sb + 16384, gB, 128, tid);
    CP_COMMIT();
    ldtile<128>(sb + 32768, gB + 16384, 128, tid);
    CP_COMMIT();

    char* smem_base = smem_raw + (sb - smem_u32(smem_raw));
    uint8_t* st8 = (uint8_t*)(smem_base + S2_EPI);
    float* zsm = (float*)(smem_base + S2_ZSM);
    uint8_t* Sp = g_S8 + (size_t)b * HW * HW;

#pragma unroll 1
    for (int it = 0; it < 4; ++it) {
        CP_WAIT(1);
        __syncthreads();            // B[it] ready; prior i-tile fully retired
        if (it + 2 < 4)
            ldtile<128>(sb + 16384 + ((it + 2) % 3) * 16384,
                        gB + (size_t)(it + 2) * 16384, 128, tid);
        CP_COMMIT();

        uint32_t sA = sb;
        uint32_t sB = sb + 16384 + (it % 3) * 16384;
        float acc[4][4][4] = {};
#pragma unroll
        for (int kt = 0; kt < 4; ++kt) {
            uint32_t af[4][4], bfr[2][4];
            int s16 = kt * 2 + (lane >> 4);
#pragma unroll
            for (int mt = 0; mt < 4; ++mt) {
                int row = wm * 64 + mt * 16 + (lane & 15);
                ldsm4(af[mt], sA + row * 128 + ((s16 ^ (row & 7)) << 4));
            }
#pragma unroll
            for (int g = 0; g < 2; ++g) {
                int row = wn * 32 + g * 16 + (lane & 15);
                ldsm4(bfr[g], sB + row * 128 + ((s16 ^ (row & 7)) << 4));
            }
#pragma unroll
            for (int mt = 0; mt < 4; ++mt)
#pragma unroll
                for (int nt = 0; nt < 4; ++nt)
                    mma_bf16(acc[mt][nt], af[mt],
                             bfr[nt >> 1][nt & 1], bfr[nt >> 1][(nt & 1) + 2]);
        }

        // ---- epilogue for this i-tile ----
        const int n0 = i0 + it * 128;
        const int r0 = wm * 64 + (lane >> 2);
        const int c0 = wn * 32 + 2 * (lane & 3);
        float zc[8] = {0, 0, 0, 0, 0, 0, 0, 0};
#pragma unroll
        for (int mt = 0; mt < 4; ++mt)
#pragma unroll
            for (int nt = 0; nt < 4; ++nt) {
                float v0 = ex2f(acc[mt][nt][0]), v1 = ex2f(acc[mt][nt][1]);
                float v2 = ex2f(acc[mt][nt][2]), v3 = ex2f(acc[mt][nt][3]);
                zc[nt * 2 + 0] += v0 + v2;
                zc[nt * 2 + 1] += v1 + v3;
                int r = r0 + mt * 16, c = c0 + nt * 8;
                *(uint16_t*)&st8[r * S8_STRIDE + c] = pack2_e4m3(v0, v1);
                *(uint16_t*)&st8[(r + 8) * S8_STRIDE + c] = pack2_e4m3(v2, v3);
            }
        // reduce over the 8 row-lanes (lane bits 2..4); deterministic order
#pragma unroll
        for (int off = 4; off <= 16; off <<= 1)
#pragma unroll
            for (int k = 0; k < 8; ++k)
                zc[k] += __shfl_xor_sync(0xffffffffu, zc[k], off);
        if ((lane >> 2) == 0) {
#pragma unroll
            for (int nt = 0; nt < 4; ++nt) {
                int col = wn * 32 + 2 * (lane & 3) + nt * 8;
                zsm[wm * 128 + col]     = zc[nt * 2 + 0];
                zsm[wm * 128 + col + 1] = zc[nt * 2 + 1];
            }
        }
        __syncthreads();
        // pure copy smem -> gmem (coalesced)
        int ch = tid & 31, h = tid >> 5;
#pragma unroll
        for (int r = 0; r < 16; ++r) {
            int row = h * 16 + r;
            *(uint32_t*)&Sp[(size_t)(m0 + row) * HW + n0 + ch * 4] =
                *(uint32_t*)&st8[row * S8_STRIDE + ch * 4];
        }
        if (tid < 128)
            g_Zp[((size_t)b * 32 + blockIdx.y) * HW + n0 + tid] =
                zsm[tid] + zsm[128 + tid];
    }
}

// ---------------------------------------------------------------------------
// HMMA GEMM (256 thr, 2 CTA/SM, 64x32 warp tiles): D[128x128] = A * B^T
// MODE 3 (bf16): Vz A=Wv(c)  B=Ut(i)  K=256el -> Vz8[c][i] = e4m3(V*4096/Z)
// MODE 4 (fp8):  Out A=Vz8(c) B=S8(j) K=4096el-> out=gamma/4096*x+U
// ---------------------------------------------------------------------------
template<int MODE>
__global__ void __launch_bounds__(256, 2) gemm_hmma(const float* __restrict__ U,
                                                    const float* __restrict__ gammap,
                                                    float* __restrict__ Out)
{
    extern __shared__ char smem_raw[];
    uint32_t sb = (smem_u32(smem_raw) + 127u) & ~127u;
    const int tid = threadIdx.x, lane = tid & 31, wid = tid >> 5;
    const int wm = wid & 1, wn = wid >> 1;
    const int b = blockIdx.z;
    const int m0 = blockIdx.y * 128, n0 = blockIdx.x * 128;

    constexpr int NC = (MODE == 3) ? 4 : 32;

    const char *gA, *gB;
    size_t strA, strB;
    if (MODE == 3) {
        gA = (const char*)(g_Wv + (size_t)m0 * CCH);            strA = CCH * 2;
        gB = (const char*)(g_Ut + ((size_t)b * HW + n0) * CCH); strB = CCH * 2;
    } else {
        gA = (const char*)(g_Vz8 + (size_t)b * CCH * HW + (size_t)m0 * HW); strA = HW;
        gB = (const char*)(g_S8 + (size_t)b * HW * HW + (size_t)n0 * HW);   strB = HW;
    }

    float acc[4][4][4] = {};

    ldtile<128>(sb, gA, strA, tid);
    ldtile<128>(sb + 16384, gB, strB, tid);
    CP_COMMIT();
    ldtile<128>(sb + STAGE_SM, gA + 128, strA, tid);
    ldtile<128>(sb + STAGE_SM + 16384, gB + 128, strB, tid);
    CP_COMMIT();

#pragma unroll 1
    for (int n = 0; n < NC; ++n) {
        CP_WAIT(1);
        __syncthreads();
        if (n + 2 < NC) {
            uint32_t sp = sb + ((n + 2) % 3) * STAGE_SM;
            ldtile<128>(sp, gA + (size_t)(n + 2) * 128, strA, tid);
            ldtile<128>(sp + 16384, gB + (size_t)(n + 2) * 128, strB, tid);
        }
        CP_COMMIT();

        uint32_t sA = sb + (n % 3) * STAGE_SM;
        uint32_t sB = sA + 16384;
#pragma unroll
        for (int kt = 0; kt < 4; ++kt) {
            uint32_t af[4][4], bfr[2][4];
            int s16 = kt * 2 + (lane >> 4);
#pragma unroll
            for (int mt = 0; mt < 4; ++mt) {
                int row = wm * 64 + mt * 16 + (lane & 15);
                ldsm4(af[mt], sA + row * 128 + ((s16 ^ (row & 7)) << 4));
            }
#pragma unroll
            for (int g = 0; g < 2; ++g) {
                int row = wn * 32 + g * 16 + (lane & 15);
                ldsm4(bfr[g], sB + row * 128 + ((s16 ^ (row & 7)) << 4));
            }
#pragma unroll
            for (int mt = 0; mt < 4; ++mt)
#pragma unroll
                for (int nt = 0; nt < 4; ++nt) {
                    if (MODE == 4)
                        mma_fp8(acc[mt][nt], af[mt],
                                bfr[nt >> 1][nt & 1], bfr[nt >> 1][(nt & 1) + 2]);
                    else
                        mma_bf16(acc[mt][nt], af[mt],
                                 bfr[nt >> 1][nt & 1], bfr[nt >> 1][(nt & 1) + 2]);
                }
        }
    }
    CP_WAIT(0);
    __syncthreads();

    const int r0 = wm * 64 + (lane >> 2);
    const int c0 = wn * 32 + 2 * (lane & 3);

    if (MODE == 3) {
        float* st = (float*)(smem_raw + (sb - smem_u32(smem_raw)));
#pragma unroll
        for (int mt = 0; mt < 4; ++mt)
#pragma unroll
            for (int nt = 0; nt < 4; ++nt) {
                int r = r0 + mt * 16, c = c0 + nt * 8;
                *(float2*)&st[r * EPI_STRIDE + c] = make_float2(acc[mt][nt][0], acc[mt][nt][1]);
                *(float2*)&st[(r + 8) * EPI_STRIDE + c] = make_float2(acc[mt][nt][2], acc[mt][nt][3]);
            }
        __syncthreads();
#pragma unroll
        for (int u = 0; u < 16; ++u) {
            int idx = tid + u * 256;
            int row = idx >> 5, ch = idx & 31;
            float4 v = *(float4*)&st[row * EPI_STRIDE + ch * 4];
            float4 z = *(const float4*)&g_Zi[b * HW + n0 + ch * 4];   // = 4096/Z
            uint32_t p = pack4_e4m3(v.x * z.x, v.y * z.y, v.z * z.z, v.w * z.w);
            *(uint32_t*)&g_Vz8[((size_t)b * CCH + m0 + row) * HW + n0 + ch * 4] = p;
        }
    } else {  // MODE 4
        float* st = (float*)(smem_raw + (sb - smem_u32(smem_raw)));
        float gamma = __ldg(gammap) * (1.0f / 4096.0f);
#pragma unroll
        for (int mt = 0; mt < 4; ++mt)
#pragma unroll
            for (int nt = 0; nt < 4; ++nt) {
                int r = r0 + mt * 16, c = c0 + nt * 8;
                *(float2*)&st[r * EPI_STRIDE + c] = make_float2(acc[mt][nt][0], acc[mt][nt][1]);
                *(float2*)&st[(r + 8) * EPI_STRIDE + c] = make_float2(acc[mt][nt][2], acc[mt][nt][3]);
            }
        __syncthreads();
#pragma unroll
        for (int u = 0; u < 16; ++u) {
            int idx = tid + u * 256;
            int row = idx >> 5, ch = idx & 31;
            float4 v = *(float4*)&st[row * EPI_STRIDE + ch * 4];
            size_t off = ((size_t)b * CCH + m0 + row) * HW + n0 + ch * 4;
            float4 uv = *(const float4*)(U + off);
            float4 o;
            o.x = fmaf(gamma, v.x, uv.x); o.y = fmaf(gamma, v.y, uv.y);
            o.z = fmaf(gamma, v.z, uv.z); o.w = fmaf(gamma, v.w, uv.w);
            *(float4*)(Out + off) = o;
        }
    }
}

// ---------------------------------------------------------------------------
// A' GEMM: D[128 x 64] = Ut(128 j-rows, K=256) * Mt(64 m-rows, K=256)^T
// Epilogue scales by log2e so mode-2 can use bare ex2.
// ---------------------------------------------------------------------------
__global__ void __launch_bounds__(256, 2) gemm_at()
{
    extern __shared__ char smem_raw[];
    uint32_t sb = (smem_u32(smem_raw) + 127u) & ~127u;
    const int tid = threadIdx.x, lane = tid & 31, wid = tid >> 5;
    const int wm = wid >> 1, wn = wid & 1;
    const int b = blockIdx.z;
    const int m0 = blockIdx.y * 128;

    constexpr int NC = CCH / 64;   // 4
    const char* gA = (const char*)(g_Ut + ((size_t)b * HW + m0) * CCH);
    const char* gB = (const char*)g_Mt;
    const size_t strA = CCH * 2, strB = CCH * 2;

    float acc[2][4][4] = {};

    ldtile<128>(sb, gA, strA, tid);
    ldtile<64>(sb + 16384, gB, strB, tid);
    CP_COMMIT();
    ldtile<128>(sb + STAGE_AT, gA + 128, strA, tid);
    ldtile<64>(sb + STAGE_AT + 16384, gB + 128, strB, tid);
    CP_COMMIT();

#pragma unroll 1
    for (int n = 0; n < NC; ++n) {
        CP_WAIT(1);
        __syncthreads();
        if (n + 2 < NC) {
            uint32_t sp = sb + ((n + 2) % 3) * STAGE_AT;
            ldtile<128>(sp, gA + (size_t)(n + 2) * 128, strA, tid);
            ldtile<64>(sp + 16384, gB + (size_t)(n + 2) * 128, strB, tid);
        }
        CP_COMMIT();

        uint32_t sA = sb + (n % 3) * STAGE_AT;
        uint32_t sB = sA + 16384;
#pragma unroll
        for (int kt = 0; kt < 4; ++kt) {
            uint32_t af[2][4], bfr[2][4];
            int s16 = kt * 2 + (lane >> 4);
#pragma unroll
            for (int mt = 0; mt < 2; ++mt) {
                int row = wm * 32 + mt * 16 + (lane & 15);
                ldsm4(af[mt], sA + row * 128 + ((s16 ^ (row & 7)) << 4));
            }
#pragma unroll
            for (int g = 0; g < 2; ++g) {
                int row = wn * 32 + g * 16 + (lane & 15);
                ldsm4(bfr[g], sB + row * 128 + ((s16 ^ (row & 7)) << 4));
            }
#pragma unroll
            for (int mt = 0; mt < 2; ++mt)
#pragma unroll
                for (int nt = 0; nt < 4; ++nt)
                    mma_bf16(acc[mt][nt], af[mt],
                             bfr[nt >> 1][nt & 1], bfr[nt >> 1][(nt & 1) + 2]);
        }
    }
    CP_WAIT(0);
    __syncthreads();

    const float LOG2E = 1.4426950408889634f;
    const int r0 = wm * 32 + (lane >> 2);
    const int c0 = wn * 32 + 2 * (lane & 3);
    bf16* st = (bf16*)(smem_raw + (sb - smem_u32(smem_raw)));
#pragma unroll
    for (int mt = 0; mt < 2; ++mt)
#pragma unroll
        for (int nt = 0; nt < 4; ++nt) {
            int r = r0 + mt * 16, c = c0 + nt * 8;
            *(__nv_bfloat162*)&st[r * 72 + c] =
                __floats2bfloat162_rn(acc[mt][nt][0] * LOG2E, acc[mt][nt][1] * LOG2E);
            *(__nv_bfloat162*)&st[(r + 8) * 72 + c] =
                __floats2bfloat162_rn(acc[mt][nt][2] * LOG2E, acc[mt][nt][3] * LOG2E);
        }
    __syncthreads();
    bf16* dst = g_At + ((size_t)b * HW + m0) * MID;
#pragma unroll
    for (int u = 0; u < 8; ++u) {
        int idx = tid + u * 256;
        int row = idx >> 4, ch = idx & 15;
        uint2 v = *(uint2*)&st[row * 72 + ch * 4];
        *(uint2*)&dst[(size_t)row * MID + ch * 4] = v;
    }
}

// ---------------------------------------------------------------------------
// Fused prep: keymid (blocks 0..4095) + wconv (4096..4351) + wmix (4352..4415)
// ---------------------------------------------------------------------------
__global__ void prep_kernel(const float* __restrict__ bmap,
                            const float* __restrict__ w1,
                            const float* __restrict__ bs,
                            const float* __restrict__ bbias,
                            const float* __restrict__ bmean,
                            const float* __restrict__ bvar,
                            const float* __restrict__ qw,
                            const float* __restrict__ vw,
                            const float* __restrict__ kw2)
{
    int blk = blockIdx.x, tid = threadIdx.x;
    if (blk < 4096) {               // keymid: Tt[b][p][m]
        int idx = blk * 256 + tid;
        int m = idx & 63, p = (idx >> 6) & (HW - 1), b = idx >> 18;
        float inv = bs[m] * rsqrtf(bvar[m] + 1e-5f);
        float a   = w1[m] * inv;
        float bb  = bbias[m] - bmean[m] * inv;
        int y = p >> 6, x = p & 63;
        float s = bmap[b * 16384 + y * 256 + x * 2];
        g_Tt[idx] = __float2bfloat16(fmaxf(fmaf(a, s, bb), 0.0f));
    } else if (blk < 4352) {        // wconv: Wv bf16
        int i = (blk - 4096) * 256 + tid;
        g_Wv[i] = __float2bfloat16(vw[i]);
    } else {                        // wmix: Mt[m][c] = sum_o Wq[o][c] Wk2[o][m]
        int m = blk - 4352, c = tid;
        float acc = 0.0f;
#pragma unroll 8
        for (int o = 0; o < CCH; ++o)
            acc += qw[o * CCH + c] * kw2[o * MID + m];
        g_Mt[m * CCH + c] = __float2bfloat16(acc);
    }
}

__global__ void transU_kernel(const float* __restrict__ U) {
    __shared__ float t[32][33];
    int b = blockIdx.z, c0 = blockIdx.y * 32, j0 = blockIdx.x * 32;
    int tx = threadIdx.x, ty = threadIdx.y;
    const float* Ub = U + ((size_t)b * CCH + c0) * HW + j0;
#pragma unroll
    for (int k = 0; k < 4; ++k)
        t[ty + 8 * k][tx] = Ub[(size_t)(ty + 8 * k) * HW + tx];
    __syncthreads();
    bf16* Utb = g_Ut + ((size_t)b * HW + j0) * CCH + c0;
#pragma unroll
    for (int k = 0; k < 4; ++k)
        Utb[(size_t)(ty + 8 * k) * CCH + tx] = __float2bfloat16(t[tx][ty + 8 * k]);
}

__global__ void zinv_kernel() {
    int t = blockIdx.x * 256 + threadIdx.x;     // BATCH*HW
    int b = t >> 12, i = t & (HW - 1);
    float s = 0.0f;
#pragma unroll
    for (int p = 0; p < 32; ++p)
        s += g_Zp[((size_t)b * 32 + p) * HW + i];
    g_Zi[t] = 4096.0f / s;       // 4096 scale folded here (undone by gamma/4096)
}

// ---------------------------------------------------------------------------
extern "C" void kernel_launch(void* const* d_in, const int* in_sizes, int n_in,
                              void* d_out, int out_size)
{
    const float* bmap     = (const float*)d_in[0];
    const float* U        = (const float*)d_in[1];
    const float* key_w1   = (const float*)d_in[2];
    const float* bn_scale = (const float*)d_in[3];
    const float* bn_bias  = (const float*)d_in[4];
    const float* bn_mean  = (const float*)d_in[5];
    const float* bn_var   = (const float*)d_in[6];
    const float* key_w2   = (const float*)d_in[7];
    const float* query_w  = (const float*)d_in[8];
    const float* value_w  = (const float*)d_in[9];
    const float* gamma    = (const float*)d_in[10];
    float* out = (float*)d_out;

    cudaFuncSetAttribute(gemm_s,       cudaFuncAttributeMaxDynamicSharedMemorySize, SMEM_S2);
    cudaFuncSetAttribute(gemm_hmma<3>, cudaFuncAttributeMaxDynamicSharedMemorySize, SMEM_SM);
    cudaFuncSetAttribute(gemm_hmma<4>, cudaFuncAttributeMaxDynamicSharedMemorySize, SMEM_SM);
    cudaFuncSetAttribute(gemm_at,      cudaFuncAttributeMaxDynamicSharedMemorySize, SMEM_AT);

    // 1) fused prep (Tt, Wv-bf16, Mt)
    prep_kernel<<<4416, 256>>>(bmap, key_w1, bn_scale, bn_bias, bn_mean, bn_var,
                               query_w, value_w, key_w2);
    // 2) Ut[b][j][c]
    transU_kernel<<<dim3(HW / 32, CCH / 32, BATCH), dim3(32, 8)>>>(U);
    // 3) A'[j][m] = (Ut . Mt^T) * log2e
    gemm_at<<<dim3(1, 32, BATCH), 256, SMEM_AT>>>();
    // 4) S8[j][i] = e4m3(2^(A'_j . T_i)) + reduced Z partials  (128x512/CTA) [profiled]
    gemm_s<<<dim3(8, 32, BATCH), 256, SMEM_S2>>>();
    // 5) Zi = 4096/Z
    zinv_kernel<<<(BATCH * HW) / 256, 256>>>();
    // 6) Vz8[c][i] = e4m3((Wv @ U)[c][i] * 4096/Z[i])
    gemm_hmma<3><<<dim3(32, 2, BATCH), 256, SMEM_SM>>>(U, gamma, out);
    // 7) out[c][j] = gamma/4096 * sum_i Vz8[c][i] S8[j][i] + U[c][j]   (fp8)
    gemm_hmma<4><<<dim3(32, 2, BATCH), 256, SMEM_SM>>>(U, gamma, out);
}